// round 1
// baseline (speedup 1.0000x reference)
#include <cuda_runtime.h>
#include <cuda_bf16.h>
#include <math.h>

// Problem constants
#define BATCH 2
#define SEQ   2048
#define DMODEL 768
#define NHEAD 12
#define DK    64
#define D3    (3*DMODEL)
#define MROWS (BATCH*SEQ)          // 4096
#define QK_SCALE 0.125f            // 1/sqrt(64)

// Scratch (device globals; no allocation allowed)
__device__ float g_qkv[(size_t)MROWS * D3];     // (B*L, 3D)  ~37.7 MB
__device__ float g_y  [(size_t)MROWS * DMODEL]; // (B*L, D)   ~12.6 MB

// ---------------------------------------------------------------------------
// Classic fp32 tiled GEMM with bias: C[M,N] = A[M,K] @ B[K,N] + bias[N]
// BM=BN=128, BK=16, 256 threads, 8x8 register tile per thread.
// All dims here are multiples of the tile sizes (4096/2304/768/128/16) so no
// bounds checks.
// ---------------------------------------------------------------------------
#define GBM 128
#define GBN 128
#define GBK 16
#define GTM 8
#define GTN 8

__global__ __launch_bounds__(256)
void sgemm_bias(const float* __restrict__ A, const float* __restrict__ B,
                const float* __restrict__ bias, float* __restrict__ C,
                int M, int N, int K)
{
    __shared__ float As[GBK][GBM];   // transposed A tile
    __shared__ float Bs[GBK][GBN];

    const int bx = blockIdx.x;       // along N
    const int by = blockIdx.y;       // along M
    const int tid = threadIdx.x;

    const int tx = (tid % (GBN / GTN)) * GTN;  // 0..120 step 8
    const int ty = (tid / (GBN / GTN)) * GTM;  // 0..120 step 8

    float acc[GTM][GTN];
#pragma unroll
    for (int i = 0; i < GTM; i++)
#pragma unroll
        for (int j = 0; j < GTN; j++) acc[i][j] = 0.0f;

    const float* Ab = A + (size_t)by * GBM * K;
    const float* Bb = B + (size_t)bx * GBN;

    for (int kt = 0; kt < K; kt += GBK) {
        // Load A tile: 128x16 = 512 float4 slots, 2 per thread
#pragma unroll
        for (int s = tid; s < (GBM * GBK) / 4; s += 256) {
            int row = s >> 2;             // 4 float4 per row
            int kc  = (s & 3) * 4;
            float4 v = *(const float4*)(Ab + (size_t)row * K + kt + kc);
            As[kc + 0][row] = v.x;
            As[kc + 1][row] = v.y;
            As[kc + 2][row] = v.z;
            As[kc + 3][row] = v.w;
        }
        // Load B tile: 16x128 = 512 float4 slots
#pragma unroll
        for (int s = tid; s < (GBK * GBN) / 4; s += 256) {
            int row = s >> 5;             // 32 float4 per row
            int c4  = (s & 31);
            float4 v = *(const float4*)(Bb + (size_t)(kt + row) * N + c4 * 4);
            *(float4*)(&Bs[row][c4 * 4]) = v;
        }
        __syncthreads();

#pragma unroll
        for (int k = 0; k < GBK; k++) {
            float a[GTM], b[GTN];
#pragma unroll
            for (int i = 0; i < GTM; i++) a[i] = As[k][ty + i];
#pragma unroll
            for (int j = 0; j < GTN; j++) b[j] = Bs[k][tx + j];
#pragma unroll
            for (int i = 0; i < GTM; i++)
#pragma unroll
                for (int j = 0; j < GTN; j++)
                    acc[i][j] = fmaf(a[i], b[j], acc[i][j]);
        }
        __syncthreads();
    }

    // Write back with bias
#pragma unroll
    for (int i = 0; i < GTM; i++) {
        float* Cp = C + (size_t)(by * GBM + ty + i) * N + bx * GBN + tx;
#pragma unroll
        for (int j = 0; j < GTN; j += 4) {
            float4 v;
            v.x = acc[i][j + 0] + bias[bx * GBN + tx + j + 0];
            v.y = acc[i][j + 1] + bias[bx * GBN + tx + j + 1];
            v.z = acc[i][j + 2] + bias[bx * GBN + tx + j + 2];
            v.w = acc[i][j + 3] + bias[bx * GBN + tx + j + 3];
            *(float4*)(Cp + j) = v;
        }
    }
}

// ---------------------------------------------------------------------------
// Causal flash attention, fp32.
// grid = (SEQ/128, BATCH*NHEAD), block = 128 threads.
// One thread owns one query row: q (64 regs), o (64 regs), online softmax.
// K/V tiles (64 keys x 64 dims) staged in shared memory; all compute reads of
// Ks/Vs are warp-uniform broadcasts (conflict-free).
// ---------------------------------------------------------------------------
#define AT_BQ 128
#define AT_BK 64

__global__ __launch_bounds__(128)
void attn_kernel()
{
    __shared__ float Ks[AT_BK][DK];
    __shared__ float Vs[AT_BK][DK];

    const int tid = threadIdx.x;
    const int bh  = blockIdx.y;
    const int b   = bh / NHEAD;
    const int h   = bh % NHEAD;
    const int q0  = blockIdx.x * AT_BQ;
    const int qrow = q0 + tid;

    // Load and pre-scale this thread's query row
    float q[DK];
    const float* qptr = g_qkv + (size_t)(b * SEQ + qrow) * D3 + h * DK;
#pragma unroll
    for (int d = 0; d < DK; d += 4) {
        float4 v = *(const float4*)(qptr + d);
        q[d + 0] = v.x * QK_SCALE;
        q[d + 1] = v.y * QK_SCALE;
        q[d + 2] = v.z * QK_SCALE;
        q[d + 3] = v.w * QK_SCALE;
    }

    float m = -1e30f, l = 0.0f;
    float o[DK];
#pragma unroll
    for (int d = 0; d < DK; d++) o[d] = 0.0f;

    const int nkt = q0 / AT_BK + 2;   // key tiles covering up to q0+127

    for (int kt = 0; kt < nkt; kt++) {
        const int k0 = kt * AT_BK;

        // Cooperative load of K and V tiles (each 64x64 f32)
#pragma unroll
        for (int s = tid; s < (AT_BK * DK) / 4; s += AT_BQ) {
            int row = s >> 4;          // 16 float4 per row
            int c4  = (s & 15);
            size_t base = (size_t)(b * SEQ + k0 + row) * D3 + h * DK + c4 * 4;
            ((float4*)Ks)[s] = *(const float4*)(g_qkv + base + DMODEL);
            ((float4*)Vs)[s] = *(const float4*)(g_qkv + base + 2 * DMODEL);
        }
        __syncthreads();

        if (qrow >= k0) {
            for (int j0 = 0; j0 < AT_BK; j0 += 16) {
                if (k0 + j0 > qrow) break;
                float s[16];
                float mt = -1e30f;
#pragma unroll
                for (int jj = 0; jj < 16; jj++) {
                    float acc = 0.0f;
#pragma unroll
                    for (int d = 0; d < DK; d++)
                        acc = fmaf(q[d], Ks[j0 + jj][d], acc);
                    if (k0 + j0 + jj > qrow) acc = -1e30f;  // causal mask
                    s[jj] = acc;
                    mt = fmaxf(mt, acc);
                }
                if (mt > m) {
                    float c = __expf(m - mt);
                    l *= c;
#pragma unroll
                    for (int d = 0; d < DK; d++) o[d] *= c;
                    m = mt;
                }
#pragma unroll
                for (int jj = 0; jj < 16; jj++) {
                    float p = __expf(s[jj] - m);
                    l += p;
#pragma unroll
                    for (int d = 0; d < DK; d++)
                        o[d] = fmaf(p, Vs[j0 + jj][d], o[d]);
                }
            }
        }
        __syncthreads();
    }

    const float inv = 1.0f / l;
    float* yp = g_y + (size_t)(b * SEQ + qrow) * DMODEL + h * DK;
#pragma unroll
    for (int d = 0; d < DK; d += 4) {
        float4 v;
        v.x = o[d + 0] * inv;
        v.y = o[d + 1] * inv;
        v.z = o[d + 2] * inv;
        v.w = o[d + 3] * inv;
        *(float4*)(yp + d) = v;
    }
}

// ---------------------------------------------------------------------------
// Launch
// Inputs (metadata order): x, mask, Wqkv, bqkv, Wo, bo. Output: f32 (B,L,D).
// mask is the fixed causal additive mask; causality is applied directly in
// the attention kernel.
// ---------------------------------------------------------------------------
extern "C" void kernel_launch(void* const* d_in, const int* in_sizes, int n_in,
                              void* d_out, int out_size)
{
    const float* x    = (const float*)d_in[0];
    // d_in[1] = mask (unused; exact causal mask applied analytically)
    const float* Wqkv = (const float*)d_in[2];
    const float* bqkv = (const float*)d_in[3];
    const float* Wo   = (const float*)d_in[4];
    const float* bo   = (const float*)d_in[5];
    float* out        = (float*)d_out;

    float* qkv_ptr = nullptr;
    float* y_ptr   = nullptr;
    cudaGetSymbolAddress((void**)&qkv_ptr, g_qkv);
    cudaGetSymbolAddress((void**)&y_ptr,   g_y);

    // 1) QKV projection: (4096 x 768) @ (768 x 2304) + bqkv
    {
        dim3 grid(D3 / GBN, MROWS / GBM);   // (18, 32)
        sgemm_bias<<<grid, 256>>>(x, Wqkv, bqkv, qkv_ptr, MROWS, D3, DMODEL);
    }

    // 2) Causal attention per (batch, head)
    {
        dim3 grid(SEQ / AT_BQ, BATCH * NHEAD);   // (16, 24)
        attn_kernel<<<grid, 128>>>();
    }

    // 3) Output projection: (4096 x 768) @ (768 x 768) + bo
    {
        dim3 grid(DMODEL / GBN, MROWS / GBM);   // (6, 32)
        sgemm_bias<<<grid, 256>>>(y_ptr, Wo, bo, out, MROWS, DMODEL, DMODEL);
    }
}

// round 2
// speedup vs baseline: 1.3609x; 1.3609x over previous
#include <cuda_runtime.h>
#include <cuda_bf16.h>
#include <math.h>

// Problem constants
#define BATCH 2
#define SEQ   2048
#define DMODEL 768
#define NHEAD 12
#define DK    64
#define D3    (3*DMODEL)
#define MROWS (BATCH*SEQ)          // 4096
#define QK_SCALE 0.125f            // 1/sqrt(64)

// Scratch (device globals; no allocation allowed)
__device__ float g_qkv[(size_t)MROWS * D3];     // (B*L, 3D)  ~37.7 MB
__device__ float g_y  [(size_t)MROWS * DMODEL]; // (B*L, D)   ~12.6 MB

// ---------------------------------------------------------------------------
// fp32 tiled GEMM with bias: C[M,N] = A[M,K] @ B[K,N] + bias[N]
// (unchanged from R1 — 27 TF/s, ~70% of FFMA ceiling)
// ---------------------------------------------------------------------------
#define GBM 128
#define GBN 128
#define GBK 16
#define GTM 8
#define GTN 8

__global__ __launch_bounds__(256)
void sgemm_bias(const float* __restrict__ A, const float* __restrict__ B,
                const float* __restrict__ bias, float* __restrict__ C,
                int M, int N, int K)
{
    __shared__ float As[GBK][GBM];   // transposed A tile
    __shared__ float Bs[GBK][GBN];

    const int bx = blockIdx.x;       // along N
    const int by = blockIdx.y;       // along M
    const int tid = threadIdx.x;

    const int tx = (tid % (GBN / GTN)) * GTN;
    const int ty = (tid / (GBN / GTN)) * GTM;

    float acc[GTM][GTN];
#pragma unroll
    for (int i = 0; i < GTM; i++)
#pragma unroll
        for (int j = 0; j < GTN; j++) acc[i][j] = 0.0f;

    const float* Ab = A + (size_t)by * GBM * K;
    const float* Bb = B + (size_t)bx * GBN;

    for (int kt = 0; kt < K; kt += GBK) {
#pragma unroll
        for (int s = tid; s < (GBM * GBK) / 4; s += 256) {
            int row = s >> 2;
            int kc  = (s & 3) * 4;
            float4 v = *(const float4*)(Ab + (size_t)row * K + kt + kc);
            As[kc + 0][row] = v.x;
            As[kc + 1][row] = v.y;
            As[kc + 2][row] = v.z;
            As[kc + 3][row] = v.w;
        }
#pragma unroll
        for (int s = tid; s < (GBK * GBN) / 4; s += 256) {
            int row = s >> 5;
            int c4  = (s & 31);
            float4 v = *(const float4*)(Bb + (size_t)(kt + row) * N + c4 * 4);
            *(float4*)(&Bs[row][c4 * 4]) = v;
        }
        __syncthreads();

#pragma unroll
        for (int k = 0; k < GBK; k++) {
            float a[GTM], b[GTN];
#pragma unroll
            for (int i = 0; i < GTM; i++) a[i] = As[k][ty + i];
#pragma unroll
            for (int j = 0; j < GTN; j++) b[j] = Bs[k][tx + j];
#pragma unroll
            for (int i = 0; i < GTM; i++)
#pragma unroll
                for (int j = 0; j < GTN; j++)
                    acc[i][j] = fmaf(a[i], b[j], acc[i][j]);
        }
        __syncthreads();
    }

#pragma unroll
    for (int i = 0; i < GTM; i++) {
        float* Cp = C + (size_t)(by * GBM + ty + i) * N + bx * GBN + tx;
#pragma unroll
        for (int j = 0; j < GTN; j += 4) {
            float4 v;
            v.x = acc[i][j + 0] + bias[bx * GBN + tx + j + 0];
            v.y = acc[i][j + 1] + bias[bx * GBN + tx + j + 1];
            v.z = acc[i][j + 2] + bias[bx * GBN + tx + j + 2];
            v.w = acc[i][j + 3] + bias[bx * GBN + tx + j + 3];
            *(float4*)(Cp + j) = v;
        }
    }
}

// ---------------------------------------------------------------------------
// Causal flash attention, fp32, register-tiled (R2 redesign).
// grid = (SEQ/64, B*H), block = 256 threads.
// Q-tile 64 x K-tile 64. Thread (qy,kx) owns a 4q x 4k score tile and a
// 4q x 4d output tile over the SAME 4 query rows -> softmax rescale is
// thread-local; row max/sum reduced over 16 lanes via shfl_xor.
// LDS:FFMA ratio ~1:8, 16 independent accumulator chains.
// ---------------------------------------------------------------------------
#define AQ 64
#define AK 64
#define PST 68   // padded row stride (floats); multiple of 4 for LDS.128

__global__ __launch_bounds__(256)
void attn2_kernel()
{
    extern __shared__ float sm[];
    float* Qt = sm;                 // [DK][PST]  Qt[d*PST + q]   (scaled Q^T)
    float* Kt = Qt + AK * PST;      // [DK][PST]  Kt[d*PST + k]   (K^T)
    float* Vs = Kt + AK * PST;      // [AK][PST]  Vs[k*PST + d]
    float* Ps = Vs + AK * PST;      // [AQ][PST]  Ps[q*PST + k]

    const int tid = threadIdx.x;
    const int qy  = tid >> 4;       // 0..15  -> q rows qy*4..qy*4+3
    const int kx  = tid & 15;       // 0..15  -> k cols / d cols kx*4..kx*4+3
    const int bh  = blockIdx.y;
    const int b   = bh / NHEAD;
    const int h   = bh % NHEAD;
    const int q0  = blockIdx.x * AQ;

    // Load Q tile transposed + pre-scaled
    for (int s = tid; s < AQ * (DK / 4); s += 256) {
        int row = s >> 4;
        int c4  = (s & 15) * 4;
        float4 v = *(const float4*)(g_qkv + (size_t)(b * SEQ + q0 + row) * D3 + h * DK + c4);
        Qt[(c4 + 0) * PST + row] = v.x * QK_SCALE;
        Qt[(c4 + 1) * PST + row] = v.y * QK_SCALE;
        Qt[(c4 + 2) * PST + row] = v.z * QK_SCALE;
        Qt[(c4 + 3) * PST + row] = v.w * QK_SCALE;
    }

    float o[4][4];
    float m[4], l[4];
#pragma unroll
    for (int i = 0; i < 4; i++) {
        m[i] = -1e30f; l[i] = 0.0f;
#pragma unroll
        for (int j = 0; j < 4; j++) o[i][j] = 0.0f;
    }

    const int nkt = q0 / AK + 1;    // key tiles 0..q0/64 (last one is diagonal)

    for (int kt = 0; kt < nkt; kt++) {
        const int k0 = kt * AK;

        __syncthreads();   // previous tile's Ps/Vs readers done before overwrite
        // Load K tile transposed, V tile row-major
        for (int s = tid; s < AK * (DK / 4); s += 256) {
            int row = s >> 4;
            int c4  = (s & 15) * 4;
            size_t base = (size_t)(b * SEQ + k0 + row) * D3 + h * DK + c4;
            float4 kv = *(const float4*)(g_qkv + base + DMODEL);
            Kt[(c4 + 0) * PST + row] = kv.x;
            Kt[(c4 + 1) * PST + row] = kv.y;
            Kt[(c4 + 2) * PST + row] = kv.z;
            Kt[(c4 + 3) * PST + row] = kv.w;
            float4 vv = *(const float4*)(g_qkv + base + 2 * DMODEL);
            *(float4*)(Vs + row * PST + c4) = vv;
        }
        __syncthreads();

        // --- S = Q K^T (this block's 64x64 tile), 4x4 per thread ---
        float sacc[4][4];
#pragma unroll
        for (int i = 0; i < 4; i++)
#pragma unroll
            for (int j = 0; j < 4; j++) sacc[i][j] = 0.0f;

#pragma unroll 16
        for (int d = 0; d < DK; d++) {
            float4 qv = *(const float4*)(Qt + d * PST + qy * 4);
            float4 kv = *(const float4*)(Kt + d * PST + kx * 4);
            float qa[4] = {qv.x, qv.y, qv.z, qv.w};
            float ka[4] = {kv.x, kv.y, kv.z, kv.w};
#pragma unroll
            for (int i = 0; i < 4; i++)
#pragma unroll
                for (int j = 0; j < 4; j++)
                    sacc[i][j] = fmaf(qa[i], ka[j], sacc[i][j]);
        }

        // Causal mask — only the diagonal tile (k0 == q0) crosses it
        if (kt == nkt - 1) {
#pragma unroll
            for (int i = 0; i < 4; i++)
#pragma unroll
                for (int j = 0; j < 4; j++)
                    if (k0 + kx * 4 + j > q0 + qy * 4 + i) sacc[i][j] = -1e30f;
        }

        // --- online softmax over rows (row = 16 lanes sharing qy) ---
#pragma unroll
        for (int i = 0; i < 4; i++) {
            float mt = fmaxf(fmaxf(sacc[i][0], sacc[i][1]),
                             fmaxf(sacc[i][2], sacc[i][3]));
#pragma unroll
            for (int off = 1; off < 16; off <<= 1)
                mt = fmaxf(mt, __shfl_xor_sync(0xffffffffu, mt, off));

            float mn = fmaxf(m[i], mt);
            float c  = __expf(m[i] - mn);
            m[i] = mn;
            l[i] *= c;
#pragma unroll
            for (int j = 0; j < 4; j++) o[i][j] *= c;

            float rs = 0.0f;
#pragma unroll
            for (int j = 0; j < 4; j++) {
                float p = __expf(sacc[i][j] - mn);
                sacc[i][j] = p;
                rs += p;
            }
#pragma unroll
            for (int off = 1; off < 16; off <<= 1)
                rs += __shfl_xor_sync(0xffffffffu, rs, off);
            l[i] += rs;
        }

        // Stage P
#pragma unroll
        for (int i = 0; i < 4; i++)
            *(float4*)(Ps + (qy * 4 + i) * PST + kx * 4) =
                make_float4(sacc[i][0], sacc[i][1], sacc[i][2], sacc[i][3]);
        __syncthreads();

        // --- O += P V, 4x4 per thread (cols = d = kx*4..+3) ---
#pragma unroll 8
        for (int kq = 0; kq < AK; kq += 4) {
            float4 p0 = *(const float4*)(Ps + (qy * 4 + 0) * PST + kq);
            float4 p1 = *(const float4*)(Ps + (qy * 4 + 1) * PST + kq);
            float4 p2 = *(const float4*)(Ps + (qy * 4 + 2) * PST + kq);
            float4 p3 = *(const float4*)(Ps + (qy * 4 + 3) * PST + kq);
            float4 v0 = *(const float4*)(Vs + (kq + 0) * PST + kx * 4);
            float4 v1 = *(const float4*)(Vs + (kq + 1) * PST + kx * 4);
            float4 v2 = *(const float4*)(Vs + (kq + 2) * PST + kx * 4);
            float4 v3 = *(const float4*)(Vs + (kq + 3) * PST + kx * 4);
            float p_[4][4] = {{p0.x, p0.y, p0.z, p0.w},
                              {p1.x, p1.y, p1.z, p1.w},
                              {p2.x, p2.y, p2.z, p2.w},
                              {p3.x, p3.y, p3.z, p3.w}};
            float v_[4][4] = {{v0.x, v0.y, v0.z, v0.w},
                              {v1.x, v1.y, v1.z, v1.w},
                              {v2.x, v2.y, v2.z, v2.w},
                              {v3.x, v3.y, v3.z, v3.w}};
#pragma unroll
            for (int r = 0; r < 4; r++)
#pragma unroll
                for (int i = 0; i < 4; i++)
#pragma unroll
                    for (int j = 0; j < 4; j++)
                        o[i][j] = fmaf(p_[i][r], v_[r][j], o[i][j]);
        }
    }

    // Normalize and write out
#pragma unroll
    for (int i = 0; i < 4; i++) {
        float inv = 1.0f / l[i];
        float4 v;
        v.x = o[i][0] * inv;
        v.y = o[i][1] * inv;
        v.z = o[i][2] * inv;
        v.w = o[i][3] * inv;
        *(float4*)(g_y + (size_t)(b * SEQ + q0 + qy * 4 + i) * DMODEL + h * DK + kx * 4) = v;
    }
}

#define ATTN_SMEM (4 * AK * PST * (int)sizeof(float))   // 69632 B

// ---------------------------------------------------------------------------
// Launch: x, mask, Wqkv, bqkv, Wo, bo -> out (B,L,D) f32
// ---------------------------------------------------------------------------
extern "C" void kernel_launch(void* const* d_in, const int* in_sizes, int n_in,
                              void* d_out, int out_size)
{
    const float* x    = (const float*)d_in[0];
    // d_in[1] = mask (exact causal; applied analytically)
    const float* Wqkv = (const float*)d_in[2];
    const float* bqkv = (const float*)d_in[3];
    const float* Wo   = (const float*)d_in[4];
    const float* bo   = (const float*)d_in[5];
    float* out        = (float*)d_out;

    float* qkv_ptr = nullptr;
    float* y_ptr   = nullptr;
    cudaGetSymbolAddress((void**)&qkv_ptr, g_qkv);
    cudaGetSymbolAddress((void**)&y_ptr,   g_y);

    cudaFuncSetAttribute(attn2_kernel,
                         cudaFuncAttributeMaxDynamicSharedMemorySize, ATTN_SMEM);

    // 1) QKV projection
    {
        dim3 grid(D3 / GBN, MROWS / GBM);
        sgemm_bias<<<grid, 256>>>(x, Wqkv, bqkv, qkv_ptr, MROWS, D3, DMODEL);
    }
    // 2) Causal attention
    {
        dim3 grid(SEQ / AQ, BATCH * NHEAD);   // (32, 24)
        attn2_kernel<<<grid, 256, ATTN_SMEM>>>();
    }
    // 3) Output projection
    {
        dim3 grid(DMODEL / GBN, MROWS / GBM);
        sgemm_bias<<<grid, 256>>>(y_ptr, Wo, bo, out, MROWS, DMODEL, DMODEL);
    }
}

// round 5
// speedup vs baseline: 3.1976x; 2.3496x over previous
#include <cuda_runtime.h>
#include <cuda_bf16.h>
#include <cstdint>
#include <math.h>

// Problem constants
#define BATCH 2
#define SEQ   2048
#define DMODEL 768
#define NHEAD 12
#define DK    64
#define D3    (3*DMODEL)
#define MROWS (BATCH*SEQ)          // 4096
#define QK_SCALE 0.125f

// ---------------------------------------------------------------------------
// Scratch (device globals; no allocation allowed)
// ---------------------------------------------------------------------------
__device__ float g_qkv[(size_t)MROWS * D3];            // (B*L, 3D)
__device__ float g_y  [(size_t)MROWS * DMODEL];        // (B*L, D)
__device__ __nv_bfloat16 g_xh[(size_t)MROWS * DMODEL];
__device__ __nv_bfloat16 g_xl[(size_t)MROWS * DMODEL];
__device__ __nv_bfloat16 g_w1h[(size_t)D3 * DMODEL];   // Wqkv^T [N=2304, K=768]
__device__ __nv_bfloat16 g_w1l[(size_t)D3 * DMODEL];
__device__ __nv_bfloat16 g_w2h[(size_t)DMODEL * DMODEL]; // Wo^T [768, 768]
__device__ __nv_bfloat16 g_w2l[(size_t)DMODEL * DMODEL];
__device__ __nv_bfloat16 g_yh[(size_t)MROWS * DMODEL];
__device__ __nv_bfloat16 g_yl[(size_t)MROWS * DMODEL];

// ---------------------------------------------------------------------------
// Portable tensor-core helpers (sm_80-era PTX: compiles for target sm_103)
// ---------------------------------------------------------------------------
__device__ __forceinline__ uint32_t smem_u32(const void* p) {
    uint32_t a;
    asm("{ .reg .u64 t; cvta.to.shared.u64 t, %1; cvt.u32.u64 %0, t; }"
        : "=r"(a) : "l"(p));
    return a;
}
__device__ __forceinline__ void ldsm_x4(uint32_t& r0, uint32_t& r1,
                                        uint32_t& r2, uint32_t& r3, uint32_t addr) {
    asm volatile("ldmatrix.sync.aligned.m8n8.x4.shared.b16 {%0,%1,%2,%3}, [%4];"
                 : "=r"(r0), "=r"(r1), "=r"(r2), "=r"(r3) : "r"(addr));
}
__device__ __forceinline__ void mma16816(float* c, const uint32_t* a, const uint32_t* b) {
    asm volatile(
        "mma.sync.aligned.m16n8k16.row.col.f32.bf16.bf16.f32 "
        "{%0,%1,%2,%3}, {%4,%5,%6,%7}, {%8,%9}, {%0,%1,%2,%3};"
        : "+f"(c[0]), "+f"(c[1]), "+f"(c[2]), "+f"(c[3])
        : "r"(a[0]), "r"(a[1]), "r"(a[2]), "r"(a[3]), "r"(b[0]), "r"(b[1]));
}

// ---------------------------------------------------------------------------
// Conversion kernels
// ---------------------------------------------------------------------------
__global__ void split_kernel(const float* __restrict__ in,
                             __nv_bfloat16* __restrict__ h,
                             __nv_bfloat16* __restrict__ l, int n)
{
    int i = blockIdx.x * blockDim.x + threadIdx.x;
    if (i < n) {
        float x = in[i];
        __nv_bfloat16 hh = __float2bfloat16(x);
        h[i] = hh;
        l[i] = __float2bfloat16(x - __bfloat162float(hh));
    }
}

// W[K,N] f32 -> Th/Tl[N,K] bf16 (transposed split), 32x32 tiles
__global__ void transpose_split_kernel(const float* __restrict__ W,
                                       __nv_bfloat16* __restrict__ Th,
                                       __nv_bfloat16* __restrict__ Tl,
                                       int K, int N)
{
    __shared__ float t[32][33];
    const int n0 = blockIdx.x * 32, k0 = blockIdx.y * 32;
    const int tx = threadIdx.x, ty = threadIdx.y;   // (32, 8)
#pragma unroll
    for (int i = 0; i < 32; i += 8)
        t[ty + i][tx] = W[(size_t)(k0 + ty + i) * N + n0 + tx];
    __syncthreads();
#pragma unroll
    for (int i = 0; i < 32; i += 8) {
        float x = t[tx][ty + i];
        __nv_bfloat16 hh = __float2bfloat16(x);
        size_t o = (size_t)(n0 + ty + i) * K + k0 + tx;
        Th[o] = hh;
        Tl[o] = __float2bfloat16(x - __bfloat162float(hh));
    }
}

// ---------------------------------------------------------------------------
// Split-bf16 GEMM on mma.sync: C[M,N] = A[M,K] @ B^T + bias (fp32 out).
// Ah/Al: [M,K] bf16; Bth/Btl: [N,K] bf16 (pre-transposed; K contiguous).
// CTA tile 128x128, 8 warps (2x4) of 64x32 warp tiles, BK=64.
// smem tiles padded to stride 72 bf16 -> conflict-free ldmatrix.
// ---------------------------------------------------------------------------
#define TB_M 128
#define TB_N 128
#define TB_K 64
#define SMS  72                               // smem row stride (bf16)
#define TILE_ELEMS (128 * SMS)                // per tile
#define GEMM_SMEM  (4 * TILE_ELEMS * 2)       // 73728 B

__global__ __launch_bounds__(256)
void gemm_mma_split(const __nv_bfloat16* __restrict__ Ah,
                    const __nv_bfloat16* __restrict__ Al,
                    const __nv_bfloat16* __restrict__ Bth,
                    const __nv_bfloat16* __restrict__ Btl,
                    const float* __restrict__ bias,
                    float* __restrict__ C,
                    int M, int N, int K)
{
    extern __shared__ __nv_bfloat16 sm[];
    __nv_bfloat16* sAh = sm;
    __nv_bfloat16* sAl = sm + TILE_ELEMS;
    __nv_bfloat16* sBh = sm + 2 * TILE_ELEMS;
    __nv_bfloat16* sBl = sm + 3 * TILE_ELEMS;

    const int tid  = threadIdx.x;
    const int wid  = tid >> 5;
    const int lane = tid & 31;
    const int wm   = wid >> 2;        // 0..1 -> warp row (64 rows)
    const int wn   = wid & 3;         // 0..3 -> warp col (32 cols)
    const int m0   = blockIdx.y * TB_M;
    const int n0   = blockIdx.x * TB_N;

    float acc[4][4][4];
#pragma unroll
    for (int i = 0; i < 4; i++)
#pragma unroll
        for (int j = 0; j < 4; j++)
#pragma unroll
            for (int e = 0; e < 4; e++) acc[i][j][e] = 0.0f;

    // Precomputed ldmatrix lane addresses (element offsets within a tile)
    // A (m16k16, x4): lanes 0-15 -> rows 0-15 col 0; 16-31 -> rows 0-15 col 8
    const int a_row = lane & 15;
    const int a_col = (lane >> 4) * 8;
    // B (two n8k16 tiles per x4): n = (lane>>4)*8 + (lane&7), k = ((lane>>3)&1)*8
    const int b_row = (lane >> 4) * 8 + (lane & 7);
    const int b_col = ((lane >> 3) & 1) * 8;

    const uint32_t sAh_u = smem_u32(sAh);
    const uint32_t sAl_u = smem_u32(sAl);
    const uint32_t sBh_u = smem_u32(sBh);
    const uint32_t sBl_u = smem_u32(sBl);

    const int nchunks = K / TB_K;
    for (int c = 0; c < nchunks; c++) {
        const int k0 = c * TB_K;
        __syncthreads();
        // Load 4 tiles: 128 rows x 64 bf16 each, uint4 (8 bf16) granules
#pragma unroll
        for (int t = 0; t < 4; t++) {
            const __nv_bfloat16* src;
            __nv_bfloat16* dst;
            int rbase;
            if (t == 0)      { src = Ah;  dst = sAh; rbase = m0; }
            else if (t == 1) { src = Al;  dst = sAl; rbase = m0; }
            else if (t == 2) { src = Bth; dst = sBh; rbase = n0; }
            else             { src = Btl; dst = sBl; rbase = n0; }
#pragma unroll
            for (int s = tid; s < 1024; s += 256) {
                int row = s >> 3;
                int c8  = s & 7;
                uint4 v = *(const uint4*)(src + (size_t)(rbase + row) * K + k0 + c8 * 8);
                *(uint4*)(dst + row * SMS + c8 * 8) = v;
            }
        }
        __syncthreads();

#pragma unroll
        for (int ks = 0; ks < 4; ks++) {
            uint32_t ah[4][4], al[4][4], bh[4][2], bl[4][2];
            // A fragments: 4 m-tiles, high & low
#pragma unroll
            for (int i = 0; i < 4; i++) {
                uint32_t off = ((wm * 64 + i * 16 + a_row) * SMS + ks * 16 + a_col) * 2;
                ldsm_x4(ah[i][0], ah[i][1], ah[i][2], ah[i][3], sAh_u + off);
                ldsm_x4(al[i][0], al[i][1], al[i][2], al[i][3], sAl_u + off);
            }
            // B fragments: 4 n-tiles via 2 x4 loads each for h & l
#pragma unroll
            for (int jp = 0; jp < 2; jp++) {
                uint32_t off = ((wn * 32 + jp * 16 + b_row) * SMS + ks * 16 + b_col) * 2;
                ldsm_x4(bh[jp*2][0], bh[jp*2][1], bh[jp*2+1][0], bh[jp*2+1][1], sBh_u + off);
                ldsm_x4(bl[jp*2][0], bl[jp*2][1], bl[jp*2+1][0], bl[jp*2+1][1], sBl_u + off);
            }
            // 3-product split accumulate
#pragma unroll
            for (int i = 0; i < 4; i++)
#pragma unroll
                for (int j = 0; j < 4; j++) {
                    mma16816(acc[i][j], ah[i], bh[j]);
                    mma16816(acc[i][j], ah[i], bl[j]);
                    mma16816(acc[i][j], al[i], bh[j]);
                }
        }
    }

    // Epilogue: direct global stores with bias (C frag: rows t/4 & t/4+8, cols (t%4)*2)
    const int cr = lane >> 2;
    const int cc = (lane & 3) * 2;
#pragma unroll
    for (int i = 0; i < 4; i++) {
#pragma unroll
        for (int j = 0; j < 4; j++) {
            int row = m0 + wm * 64 + i * 16 + cr;
            int col = n0 + wn * 32 + j * 8 + cc;
            float b0 = __ldg(bias + col), b1 = __ldg(bias + col + 1);
            float2 v0 = make_float2(acc[i][j][0] + b0, acc[i][j][1] + b1);
            float2 v1 = make_float2(acc[i][j][2] + b0, acc[i][j][3] + b1);
            *(float2*)(C + (size_t)row * N + col) = v0;
            *(float2*)(C + (size_t)(row + 8) * N + col) = v1;
        }
    }
}

// ---------------------------------------------------------------------------
// Causal flash attention, fp32, register-tiled (unchanged)
// ---------------------------------------------------------------------------
#define AQ 64
#define AK 64
#define PST 68

__global__ __launch_bounds__(256)
void attn2_kernel()
{
    extern __shared__ float smf[];
    float* Qt = smf;
    float* Kt = Qt + AK * PST;
    float* Vs = Kt + AK * PST;
    float* Ps = Vs + AK * PST;

    const int tid = threadIdx.x;
    const int qy  = tid >> 4;
    const int kx  = tid & 15;
    const int bh  = blockIdx.y;
    const int b   = bh / NHEAD;
    const int h   = bh % NHEAD;
    const int q0  = blockIdx.x * AQ;

    for (int s = tid; s < AQ * (DK / 4); s += 256) {
        int row = s >> 4;
        int c4  = (s & 15) * 4;
        float4 v = *(const float4*)(g_qkv + (size_t)(b * SEQ + q0 + row) * D3 + h * DK + c4);
        Qt[(c4 + 0) * PST + row] = v.x * QK_SCALE;
        Qt[(c4 + 1) * PST + row] = v.y * QK_SCALE;
        Qt[(c4 + 2) * PST + row] = v.z * QK_SCALE;
        Qt[(c4 + 3) * PST + row] = v.w * QK_SCALE;
    }

    float o[4][4];
    float m[4], l[4];
#pragma unroll
    for (int i = 0; i < 4; i++) {
        m[i] = -1e30f; l[i] = 0.0f;
#pragma unroll
        for (int j = 0; j < 4; j++) o[i][j] = 0.0f;
    }

    const int nkt = q0 / AK + 1;

    for (int kt = 0; kt < nkt; kt++) {
        const int k0 = kt * AK;

        __syncthreads();
        for (int s = tid; s < AK * (DK / 4); s += 256) {
            int row = s >> 4;
            int c4  = (s & 15) * 4;
            size_t base = (size_t)(b * SEQ + k0 + row) * D3 + h * DK + c4;
            float4 kv = *(const float4*)(g_qkv + base + DMODEL);
            Kt[(c4 + 0) * PST + row] = kv.x;
            Kt[(c4 + 1) * PST + row] = kv.y;
            Kt[(c4 + 2) * PST + row] = kv.z;
            Kt[(c4 + 3) * PST + row] = kv.w;
            float4 vv = *(const float4*)(g_qkv + base + 2 * DMODEL);
            *(float4*)(Vs + row * PST + c4) = vv;
        }
        __syncthreads();

        float sacc[4][4];
#pragma unroll
        for (int i = 0; i < 4; i++)
#pragma unroll
            for (int j = 0; j < 4; j++) sacc[i][j] = 0.0f;

#pragma unroll 16
        for (int d = 0; d < DK; d++) {
            float4 qv = *(const float4*)(Qt + d * PST + qy * 4);
            float4 kv = *(const float4*)(Kt + d * PST + kx * 4);
            float qa[4] = {qv.x, qv.y, qv.z, qv.w};
            float ka[4] = {kv.x, kv.y, kv.z, kv.w};
#pragma unroll
            for (int i = 0; i < 4; i++)
#pragma unroll
                for (int j = 0; j < 4; j++)
                    sacc[i][j] = fmaf(qa[i], ka[j], sacc[i][j]);
        }

        if (kt == nkt - 1) {
#pragma unroll
            for (int i = 0; i < 4; i++)
#pragma unroll
                for (int j = 0; j < 4; j++)
                    if (k0 + kx * 4 + j > q0 + qy * 4 + i) sacc[i][j] = -1e30f;
        }

#pragma unroll
        for (int i = 0; i < 4; i++) {
            float mt = fmaxf(fmaxf(sacc[i][0], sacc[i][1]),
                             fmaxf(sacc[i][2], sacc[i][3]));
#pragma unroll
            for (int off = 1; off < 16; off <<= 1)
                mt = fmaxf(mt, __shfl_xor_sync(0xffffffffu, mt, off));

            float mn = fmaxf(m[i], mt);
            float c  = __expf(m[i] - mn);
            m[i] = mn;
            l[i] *= c;
#pragma unroll
            for (int j = 0; j < 4; j++) o[i][j] *= c;

            float rs = 0.0f;
#pragma unroll
            for (int j = 0; j < 4; j++) {
                float p = __expf(sacc[i][j] - mn);
                sacc[i][j] = p;
                rs += p;
            }
#pragma unroll
            for (int off = 1; off < 16; off <<= 1)
                rs += __shfl_xor_sync(0xffffffffu, rs, off);
            l[i] += rs;
        }

#pragma unroll
        for (int i = 0; i < 4; i++)
            *(float4*)(Ps + (qy * 4 + i) * PST + kx * 4) =
                make_float4(sacc[i][0], sacc[i][1], sacc[i][2], sacc[i][3]);
        __syncthreads();

#pragma unroll 8
        for (int kq = 0; kq < AK; kq += 4) {
            float4 p0 = *(const float4*)(Ps + (qy * 4 + 0) * PST + kq);
            float4 p1 = *(const float4*)(Ps + (qy * 4 + 1) * PST + kq);
            float4 p2 = *(const float4*)(Ps + (qy * 4 + 2) * PST + kq);
            float4 p3 = *(const float4*)(Ps + (qy * 4 + 3) * PST + kq);
            float4 v0 = *(const float4*)(Vs + (kq + 0) * PST + kx * 4);
            float4 v1 = *(const float4*)(Vs + (kq + 1) * PST + kx * 4);
            float4 v2 = *(const float4*)(Vs + (kq + 2) * PST + kx * 4);
            float4 v3 = *(const float4*)(Vs + (kq + 3) * PST + kx * 4);
            float p_[4][4] = {{p0.x, p0.y, p0.z, p0.w},
                              {p1.x, p1.y, p1.z, p1.w},
                              {p2.x, p2.y, p2.z, p2.w},
                              {p3.x, p3.y, p3.z, p3.w}};
            float v_[4][4] = {{v0.x, v0.y, v0.z, v0.w},
                              {v1.x, v1.y, v1.z, v1.w},
                              {v2.x, v2.y, v2.z, v2.w},
                              {v3.x, v3.y, v3.z, v3.w}};
#pragma unroll
            for (int r = 0; r < 4; r++)
#pragma unroll
                for (int i = 0; i < 4; i++)
#pragma unroll
                    for (int j = 0; j < 4; j++)
                        o[i][j] = fmaf(p_[i][r], v_[r][j], o[i][j]);
        }
    }

#pragma unroll
    for (int i = 0; i < 4; i++) {
        float inv = 1.0f / l[i];
        float4 v;
        v.x = o[i][0] * inv;
        v.y = o[i][1] * inv;
        v.z = o[i][2] * inv;
        v.w = o[i][3] * inv;
        *(float4*)(g_y + (size_t)(b * SEQ + q0 + qy * 4 + i) * DMODEL + h * DK + kx * 4) = v;
    }
}

#define ATTN_SMEM (4 * AK * PST * (int)sizeof(float))

// ---------------------------------------------------------------------------
// Launch: x, mask, Wqkv, bqkv, Wo, bo -> out (B,L,D) f32
// ---------------------------------------------------------------------------
extern "C" void kernel_launch(void* const* d_in, const int* in_sizes, int n_in,
                              void* d_out, int out_size)
{
    const float* x    = (const float*)d_in[0];
    // d_in[1] = mask (exact causal; applied analytically)
    const float* Wqkv = (const float*)d_in[2];
    const float* bqkv = (const float*)d_in[3];
    const float* Wo   = (const float*)d_in[4];
    const float* bo   = (const float*)d_in[5];
    float* out        = (float*)d_out;

    float *qkv_ptr, *y_ptr;
    __nv_bfloat16 *xh, *xl, *w1h, *w1l, *w2h, *w2l, *yh, *yl;
    cudaGetSymbolAddress((void**)&qkv_ptr, g_qkv);
    cudaGetSymbolAddress((void**)&y_ptr,   g_y);
    cudaGetSymbolAddress((void**)&xh,  g_xh);
    cudaGetSymbolAddress((void**)&xl,  g_xl);
    cudaGetSymbolAddress((void**)&w1h, g_w1h);
    cudaGetSymbolAddress((void**)&w1l, g_w1l);
    cudaGetSymbolAddress((void**)&w2h, g_w2h);
    cudaGetSymbolAddress((void**)&w2l, g_w2l);
    cudaGetSymbolAddress((void**)&yh,  g_yh);
    cudaGetSymbolAddress((void**)&yl,  g_yl);

    cudaFuncSetAttribute(attn2_kernel,
                         cudaFuncAttributeMaxDynamicSharedMemorySize, ATTN_SMEM);
    cudaFuncSetAttribute(gemm_mma_split,
                         cudaFuncAttributeMaxDynamicSharedMemorySize, GEMM_SMEM);

    // 0) Split/transpose conversions
    {
        int n = MROWS * DMODEL;
        split_kernel<<<(n + 255) / 256, 256>>>(x, xh, xl, n);
        dim3 g1(D3 / 32, DMODEL / 32);
        transpose_split_kernel<<<g1, dim3(32, 8)>>>(Wqkv, w1h, w1l, DMODEL, D3);
        dim3 g2(DMODEL / 32, DMODEL / 32);
        transpose_split_kernel<<<g2, dim3(32, 8)>>>(Wo, w2h, w2l, DMODEL, DMODEL);
    }

    // 1) QKV projection on tensor cores
    {
        dim3 grid(D3 / TB_N, MROWS / TB_M);   // (18, 32)
        gemm_mma_split<<<grid, 256, GEMM_SMEM>>>(xh, xl, w1h, w1l, bqkv, qkv_ptr,
                                                 MROWS, D3, DMODEL);
    }

    // 2) Causal attention (fp32)
    {
        dim3 grid(SEQ / AQ, BATCH * NHEAD);   // (32, 24)
        attn2_kernel<<<grid, 256, ATTN_SMEM>>>();
    }

    // 3) Split y, then output projection on tensor cores
    {
        int n = MROWS * DMODEL;
        split_kernel<<<(n + 255) / 256, 256>>>(y_ptr, yh, yl, n);
        dim3 grid(DMODEL / TB_N, MROWS / TB_M);  // (6, 32)
        gemm_mma_split<<<grid, 256, GEMM_SMEM>>>(yh, yl, w2h, w2l, bo, out,
                                                 MROWS, DMODEL, DMODEL);
    }
}

// round 6
// speedup vs baseline: 5.0765x; 1.5876x over previous
#include <cuda_runtime.h>
#include <cuda_bf16.h>
#include <cstdint>
#include <math.h>

// Problem constants
#define BATCH 2
#define SEQ   2048
#define DMODEL 768
#define NHEAD 12
#define DK    64
#define D3    (3*DMODEL)
#define MROWS (BATCH*SEQ)          // 4096
#define SCALE_LOG2E 0.1803368801111204f   // 0.125 * log2(e)

// ---------------------------------------------------------------------------
// Scratch (device globals; no allocation allowed)
// ---------------------------------------------------------------------------
__device__ __nv_bfloat16 g_qkvh[(size_t)MROWS * D3];   // split qkv (high)
__device__ __nv_bfloat16 g_qkvl[(size_t)MROWS * D3];   // split qkv (low)
__device__ __nv_bfloat16 g_xh[(size_t)MROWS * DMODEL];
__device__ __nv_bfloat16 g_xl[(size_t)MROWS * DMODEL];
__device__ __nv_bfloat16 g_w1h[(size_t)D3 * DMODEL];   // Wqkv^T [2304, 768]
__device__ __nv_bfloat16 g_w1l[(size_t)D3 * DMODEL];
__device__ __nv_bfloat16 g_w2h[(size_t)DMODEL * DMODEL]; // Wo^T
__device__ __nv_bfloat16 g_w2l[(size_t)DMODEL * DMODEL];
__device__ __nv_bfloat16 g_yh[(size_t)MROWS * DMODEL];
__device__ __nv_bfloat16 g_yl[(size_t)MROWS * DMODEL];

// ---------------------------------------------------------------------------
// Portable tensor-core helpers (sm_80-era PTX)
// ---------------------------------------------------------------------------
__device__ __forceinline__ uint32_t smem_u32(const void* p) {
    uint32_t a;
    asm("{ .reg .u64 t; cvta.to.shared.u64 t, %1; cvt.u32.u64 %0, t; }"
        : "=r"(a) : "l"(p));
    return a;
}
__device__ __forceinline__ void ldsm_x4(uint32_t& r0, uint32_t& r1,
                                        uint32_t& r2, uint32_t& r3, uint32_t addr) {
    asm volatile("ldmatrix.sync.aligned.m8n8.x4.shared.b16 {%0,%1,%2,%3}, [%4];"
                 : "=r"(r0), "=r"(r1), "=r"(r2), "=r"(r3) : "r"(addr));
}
__device__ __forceinline__ void ldsm_x4_t(uint32_t& r0, uint32_t& r1,
                                          uint32_t& r2, uint32_t& r3, uint32_t addr) {
    asm volatile("ldmatrix.sync.aligned.m8n8.x4.trans.shared.b16 {%0,%1,%2,%3}, [%4];"
                 : "=r"(r0), "=r"(r1), "=r"(r2), "=r"(r3) : "r"(addr));
}
__device__ __forceinline__ void mma16816(float* c, const uint32_t* a, const uint32_t* b) {
    asm volatile(
        "mma.sync.aligned.m16n8k16.row.col.f32.bf16.bf16.f32 "
        "{%0,%1,%2,%3}, {%4,%5,%6,%7}, {%8,%9}, {%0,%1,%2,%3};"
        : "+f"(c[0]), "+f"(c[1]), "+f"(c[2]), "+f"(c[3])
        : "r"(a[0]), "r"(a[1]), "r"(a[2]), "r"(a[3]), "r"(b[0]), "r"(b[1]));
}
// pack (lo, hi) floats into bf16x2 register
__device__ __forceinline__ uint32_t pack_bf16x2(float lo, float hi) {
    uint32_t r;
    asm("cvt.rn.bf16x2.f32 %0, %1, %2;" : "=r"(r) : "f"(hi), "f"(lo));
    return r;
}

// ---------------------------------------------------------------------------
// Conversion kernels
// ---------------------------------------------------------------------------
__global__ void split_kernel(const float* __restrict__ in,
                             __nv_bfloat16* __restrict__ h,
                             __nv_bfloat16* __restrict__ l, int n)
{
    int i = blockIdx.x * blockDim.x + threadIdx.x;
    if (i < n) {
        float x = in[i];
        __nv_bfloat16 hh = __float2bfloat16(x);
        h[i] = hh;
        l[i] = __float2bfloat16(x - __bfloat162float(hh));
    }
}

__global__ void transpose_split_kernel(const float* __restrict__ W,
                                       __nv_bfloat16* __restrict__ Th,
                                       __nv_bfloat16* __restrict__ Tl,
                                       int K, int N)
{
    __shared__ float t[32][33];
    const int n0 = blockIdx.x * 32, k0 = blockIdx.y * 32;
    const int tx = threadIdx.x, ty = threadIdx.y;   // (32, 8)
#pragma unroll
    for (int i = 0; i < 32; i += 8)
        t[ty + i][tx] = W[(size_t)(k0 + ty + i) * N + n0 + tx];
    __syncthreads();
#pragma unroll
    for (int i = 0; i < 32; i += 8) {
        float x = t[tx][ty + i];
        __nv_bfloat16 hh = __float2bfloat16(x);
        size_t o = (size_t)(n0 + ty + i) * K + k0 + tx;
        Th[o] = hh;
        Tl[o] = __float2bfloat16(x - __bfloat162float(hh));
    }
}

// ---------------------------------------------------------------------------
// Split-bf16 GEMM on mma.sync. Output either f32 C (+bias), or split-bf16
// (Ch, Cl) when Ch != nullptr.
// ---------------------------------------------------------------------------
#define TB_M 128
#define TB_N 128
#define TB_K 64
#define SMS  72
#define TILE_ELEMS (128 * SMS)
#define GEMM_SMEM  (4 * TILE_ELEMS * 2)   // 73728 B

__global__ __launch_bounds__(256)
void gemm_mma_split(const __nv_bfloat16* __restrict__ Ah,
                    const __nv_bfloat16* __restrict__ Al,
                    const __nv_bfloat16* __restrict__ Bth,
                    const __nv_bfloat16* __restrict__ Btl,
                    const float* __restrict__ bias,
                    float* __restrict__ C,
                    __nv_bfloat16* __restrict__ Ch,
                    __nv_bfloat16* __restrict__ Cl,
                    int M, int N, int K)
{
    extern __shared__ __nv_bfloat16 smg[];
    __nv_bfloat16* sAh = smg;
    __nv_bfloat16* sAl = smg + TILE_ELEMS;
    __nv_bfloat16* sBh = smg + 2 * TILE_ELEMS;
    __nv_bfloat16* sBl = smg + 3 * TILE_ELEMS;

    const int tid  = threadIdx.x;
    const int wid  = tid >> 5;
    const int lane = tid & 31;
    const int wm   = wid >> 2;
    const int wn   = wid & 3;
    const int m0   = blockIdx.y * TB_M;
    const int n0   = blockIdx.x * TB_N;

    float acc[4][4][4];
#pragma unroll
    for (int i = 0; i < 4; i++)
#pragma unroll
        for (int j = 0; j < 4; j++)
#pragma unroll
            for (int e = 0; e < 4; e++) acc[i][j][e] = 0.0f;

    const int a_row = lane & 15;
    const int a_col = (lane >> 4) * 8;
    const int b_row = (lane >> 4) * 8 + (lane & 7);
    const int b_col = ((lane >> 3) & 1) * 8;

    const uint32_t sAh_u = smem_u32(sAh);
    const uint32_t sAl_u = smem_u32(sAl);
    const uint32_t sBh_u = smem_u32(sBh);
    const uint32_t sBl_u = smem_u32(sBl);

    const int nchunks = K / TB_K;
    for (int c = 0; c < nchunks; c++) {
        const int k0 = c * TB_K;
        __syncthreads();
#pragma unroll
        for (int t = 0; t < 4; t++) {
            const __nv_bfloat16* src;
            __nv_bfloat16* dst;
            int rbase;
            if (t == 0)      { src = Ah;  dst = sAh; rbase = m0; }
            else if (t == 1) { src = Al;  dst = sAl; rbase = m0; }
            else if (t == 2) { src = Bth; dst = sBh; rbase = n0; }
            else             { src = Btl; dst = sBl; rbase = n0; }
#pragma unroll
            for (int s = tid; s < 1024; s += 256) {
                int row = s >> 3;
                int c8  = s & 7;
                uint4 v = *(const uint4*)(src + (size_t)(rbase + row) * K + k0 + c8 * 8);
                *(uint4*)(dst + row * SMS + c8 * 8) = v;
            }
        }
        __syncthreads();

#pragma unroll
        for (int ks = 0; ks < 4; ks++) {
            uint32_t ah[4][4], al[4][4], bh[4][2], bl[4][2];
#pragma unroll
            for (int i = 0; i < 4; i++) {
                uint32_t off = ((wm * 64 + i * 16 + a_row) * SMS + ks * 16 + a_col) * 2;
                ldsm_x4(ah[i][0], ah[i][1], ah[i][2], ah[i][3], sAh_u + off);
                ldsm_x4(al[i][0], al[i][1], al[i][2], al[i][3], sAl_u + off);
            }
#pragma unroll
            for (int jp = 0; jp < 2; jp++) {
                uint32_t off = ((wn * 32 + jp * 16 + b_row) * SMS + ks * 16 + b_col) * 2;
                ldsm_x4(bh[jp*2][0], bh[jp*2][1], bh[jp*2+1][0], bh[jp*2+1][1], sBh_u + off);
                ldsm_x4(bl[jp*2][0], bl[jp*2][1], bl[jp*2+1][0], bl[jp*2+1][1], sBl_u + off);
            }
#pragma unroll
            for (int i = 0; i < 4; i++)
#pragma unroll
                for (int j = 0; j < 4; j++) {
                    mma16816(acc[i][j], ah[i], bh[j]);
                    mma16816(acc[i][j], ah[i], bl[j]);
                    mma16816(acc[i][j], al[i], bh[j]);
                }
        }
    }

    const int cr = lane >> 2;
    const int cc = (lane & 3) * 2;
#pragma unroll
    for (int i = 0; i < 4; i++) {
#pragma unroll
        for (int j = 0; j < 4; j++) {
            int row = m0 + wm * 64 + i * 16 + cr;
            int col = n0 + wn * 32 + j * 8 + cc;
            float b0 = __ldg(bias + col), b1 = __ldg(bias + col + 1);
            float v00 = acc[i][j][0] + b0, v01 = acc[i][j][1] + b1;
            float v10 = acc[i][j][2] + b0, v11 = acc[i][j][3] + b1;
            if (Ch) {
                uint32_t h0 = pack_bf16x2(v00, v01);
                uint32_t h1 = pack_bf16x2(v10, v11);
                uint32_t l0 = pack_bf16x2(v00 - __uint_as_float(h0 << 16),
                                          v01 - __uint_as_float(h0 & 0xffff0000u));
                uint32_t l1 = pack_bf16x2(v10 - __uint_as_float(h1 << 16),
                                          v11 - __uint_as_float(h1 & 0xffff0000u));
                *(uint32_t*)(Ch + (size_t)row * N + col) = h0;
                *(uint32_t*)(Ch + (size_t)(row + 8) * N + col) = h1;
                *(uint32_t*)(Cl + (size_t)row * N + col) = l0;
                *(uint32_t*)(Cl + (size_t)(row + 8) * N + col) = l1;
            } else {
                *(float2*)(C + (size_t)row * N + col) = make_float2(v00, v01);
                *(float2*)(C + (size_t)(row + 8) * N + col) = make_float2(v10, v11);
            }
        }
    }
}

// ---------------------------------------------------------------------------
// Causal flash attention on mma.sync, split-bf16 everywhere.
// grid = (SEQ/128, B*H), 8 warps. Warp w owns q rows [q0+16w, q0+16w+16).
// K/V tiles: 64 keys. P fragments built in registers from S C-fragments.
// Writes split-bf16 y directly.
// ---------------------------------------------------------------------------
#define VST 72
#define ATT_SMEM_ELEMS (4 * 64 * VST)    // 18432 bf16 = 36864 B

__global__ __launch_bounds__(256)
void attn3_kernel()
{
    __shared__ __nv_bfloat16 sm[ATT_SMEM_ELEMS];
    __nv_bfloat16* sKh = sm;
    __nv_bfloat16* sKl = sm + 64 * VST;
    __nv_bfloat16* sVh = sm + 2 * 64 * VST;
    __nv_bfloat16* sVl = sm + 3 * 64 * VST;

    const int tid  = threadIdx.x;
    const int wq   = tid >> 5;
    const int lane = tid & 31;
    const int bh   = blockIdx.y;
    const int b    = bh / NHEAD;
    const int h    = bh % NHEAD;
    const int q0   = (gridDim.x - 1 - blockIdx.x) * 128;   // heavy blocks first

    const int a_row = lane & 15;
    const int a_col = (lane >> 4) * 8;
    const int b_row = (lane >> 4) * 8 + (lane & 7);
    const int b_col = ((lane >> 3) & 1) * 8;
    const int cr = lane >> 2;
    const int cc = (lane & 3) * 2;

    // ---- Stage Q tile (128 x 64, h & l) into smem, then frags to registers
    {
        const __nv_bfloat16* qh_src = g_qkvh + (size_t)(b * SEQ + q0) * D3 + h * DK;
        const __nv_bfloat16* ql_src = g_qkvl + (size_t)(b * SEQ + q0) * D3 + h * DK;
        for (int s = tid; s < 1024; s += 256) {
            int row = s >> 3;
            int c8  = s & 7;
            *(uint4*)(sm + row * VST + c8 * 8) =
                *(const uint4*)(qh_src + (size_t)row * D3 + c8 * 8);
            *(uint4*)(sm + 128 * VST + row * VST + c8 * 8) =
                *(const uint4*)(ql_src + (size_t)row * D3 + c8 * 8);
        }
    }
    __syncthreads();

    uint32_t qfh[4][4], qfl[4][4];
    {
        const uint32_t sq = smem_u32(sm);
#pragma unroll
        for (int t = 0; t < 4; t++) {
            uint32_t off = ((wq * 16 + a_row) * VST + t * 16 + a_col) * 2;
            ldsm_x4(qfh[t][0], qfh[t][1], qfh[t][2], qfh[t][3], sq + off);
            ldsm_x4(qfl[t][0], qfl[t][1], qfl[t][2], qfl[t][3],
                    sq + 128 * VST * 2 + off);
        }
    }
    __syncthreads();

    float oacc[8][4];
#pragma unroll
    for (int j = 0; j < 8; j++)
#pragma unroll
        for (int e = 0; e < 4; e++) oacc[j][e] = 0.0f;
    float mrow[2] = {-1e30f, -1e30f};
    float lrow[2] = {0.0f, 0.0f};

    const uint32_t sKh_u = smem_u32(sKh), sKl_u = smem_u32(sKl);
    const uint32_t sVh_u = smem_u32(sVh), sVl_u = smem_u32(sVl);
    const int warp_row_min = q0 + wq * 16;
    const int nkt = q0 / 64 + 2;

    for (int kt = 0; kt < nkt; kt++) {
        const int k0 = kt * 64;

        // Load K/V tiles (split bf16) into smem
        {
            const size_t base = (size_t)(b * SEQ + k0) * D3 + h * DK;
            for (int s = tid; s < 512; s += 256) {
                int row = s >> 3;
                int c8  = s & 7;
                size_t g = base + (size_t)row * D3 + c8 * 8;
                int so = row * VST + c8 * 8;
                *(uint4*)(sKh + so) = *(const uint4*)(g_qkvh + g + DMODEL);
                *(uint4*)(sKl + so) = *(const uint4*)(g_qkvl + g + DMODEL);
                *(uint4*)(sVh + so) = *(const uint4*)(g_qkvh + g + 2 * DMODEL);
                *(uint4*)(sVl + so) = *(const uint4*)(g_qkvl + g + 2 * DMODEL);
            }
        }
        __syncthreads();

        if (k0 <= warp_row_min + 15) {   // warp has at least one unmasked key
            // ---- S = Q K^T (16 x 64 per warp), 3-product split
            float sacc[8][4];
#pragma unroll
            for (int j = 0; j < 8; j++)
#pragma unroll
                for (int e = 0; e < 4; e++) sacc[j][e] = 0.0f;

#pragma unroll
            for (int t = 0; t < 4; t++) {
                uint32_t kbh[8][2], kbl[8][2];
#pragma unroll
                for (int jp = 0; jp < 4; jp++) {
                    uint32_t off = ((jp * 16 + b_row) * VST + t * 16 + b_col) * 2;
                    ldsm_x4(kbh[jp*2][0], kbh[jp*2][1], kbh[jp*2+1][0], kbh[jp*2+1][1],
                            sKh_u + off);
                    ldsm_x4(kbl[jp*2][0], kbl[jp*2][1], kbl[jp*2+1][0], kbl[jp*2+1][1],
                            sKl_u + off);
                }
#pragma unroll
                for (int j = 0; j < 8; j++) {
                    mma16816(sacc[j], qfh[t], kbh[j]);
                    mma16816(sacc[j], qfh[t], kbl[j]);
                    mma16816(sacc[j], qfl[t], kbh[j]);
                }
            }

            // scale to base-2 domain; causal mask on diagonal-crossing tiles
#pragma unroll
            for (int j = 0; j < 8; j++)
#pragma unroll
                for (int e = 0; e < 4; e++) sacc[j][e] *= SCALE_LOG2E;

            if (k0 + 63 > warp_row_min) {
#pragma unroll
                for (int j = 0; j < 8; j++)
#pragma unroll
                    for (int e = 0; e < 4; e++) {
                        int key = k0 + j * 8 + cc + (e & 1);
                        int row = warp_row_min + cr + ((e >> 1) * 8);
                        if (key > row) sacc[j][e] = -1e30f;
                    }
            }

            // ---- online softmax (rows cr and cr+8; 4 lanes per row)
#pragma unroll
            for (int r = 0; r < 2; r++) {
                float mt = -1e30f;
#pragma unroll
                for (int j = 0; j < 8; j++)
                    mt = fmaxf(mt, fmaxf(sacc[j][2*r], sacc[j][2*r+1]));
                mt = fmaxf(mt, __shfl_xor_sync(0xffffffffu, mt, 1));
                mt = fmaxf(mt, __shfl_xor_sync(0xffffffffu, mt, 2));

                float mn = fmaxf(mrow[r], mt);
                float c  = exp2f(mrow[r] - mn);
                mrow[r] = mn;
                lrow[r] *= c;
#pragma unroll
                for (int j = 0; j < 8; j++) {
                    oacc[j][2*r]   *= c;
                    oacc[j][2*r+1] *= c;
                }
                float rs = 0.0f;
#pragma unroll
                for (int j = 0; j < 8; j++) {
                    float p0 = exp2f(sacc[j][2*r]   - mn);
                    float p1 = exp2f(sacc[j][2*r+1] - mn);
                    sacc[j][2*r]   = p0;
                    sacc[j][2*r+1] = p1;
                    rs += p0 + p1;
                }
                lrow[r] += rs;
            }

            // ---- O += P V  (P frags from registers, V via ldmatrix.trans)
#pragma unroll
            for (int t = 0; t < 4; t++) {
                uint32_t pah[4], pal[4];
#pragma unroll
                for (int half = 0; half < 2; half++) {
                    int j = 2 * t + half;
                    uint32_t h0 = pack_bf16x2(sacc[j][0], sacc[j][1]);
                    uint32_t h1 = pack_bf16x2(sacc[j][2], sacc[j][3]);
                    pah[half*2]   = h0;
                    pah[half*2+1] = h1;
                    pal[half*2]   = pack_bf16x2(
                        sacc[j][0] - __uint_as_float(h0 << 16),
                        sacc[j][1] - __uint_as_float(h0 & 0xffff0000u));
                    pal[half*2+1] = pack_bf16x2(
                        sacc[j][2] - __uint_as_float(h1 << 16),
                        sacc[j][3] - __uint_as_float(h1 & 0xffff0000u));
                }
                uint32_t vbh[8][2], vbl[8][2];
#pragma unroll
                for (int dp = 0; dp < 4; dp++) {
                    uint32_t off = ((t * 16 + (lane & 15)) * VST + dp * 16 + (lane >> 4) * 8) * 2;
                    ldsm_x4_t(vbh[dp*2][0], vbh[dp*2][1], vbh[dp*2+1][0], vbh[dp*2+1][1],
                              sVh_u + off);
                    ldsm_x4_t(vbl[dp*2][0], vbl[dp*2][1], vbl[dp*2+1][0], vbl[dp*2+1][1],
                              sVl_u + off);
                }
#pragma unroll
                for (int j = 0; j < 8; j++) {
                    mma16816(oacc[j], pah, vbh[j]);
                    mma16816(oacc[j], pah, vbl[j]);
                    mma16816(oacc[j], pal, vbh[j]);
                }
            }
        }
        __syncthreads();
    }

    // ---- finalize: reduce l across the 4 lanes of each row, normalize, split-store
#pragma unroll
    for (int r = 0; r < 2; r++) {
        lrow[r] += __shfl_xor_sync(0xffffffffu, lrow[r], 1);
        lrow[r] += __shfl_xor_sync(0xffffffffu, lrow[r], 2);
    }
    const float inv0 = 1.0f / lrow[0];
    const float inv1 = 1.0f / lrow[1];
    const int row_a = q0 + wq * 16 + cr;
    const int row_b = row_a + 8;
    const int gb = b * SEQ;
#pragma unroll
    for (int j = 0; j < 8; j++) {
        int col = h * DK + j * 8 + cc;
        float v00 = oacc[j][0] * inv0, v01 = oacc[j][1] * inv0;
        float v10 = oacc[j][2] * inv1, v11 = oacc[j][3] * inv1;
        uint32_t h0 = pack_bf16x2(v00, v01);
        uint32_t h1 = pack_bf16x2(v10, v11);
        uint32_t l0 = pack_bf16x2(v00 - __uint_as_float(h0 << 16),
                                  v01 - __uint_as_float(h0 & 0xffff0000u));
        uint32_t l1 = pack_bf16x2(v10 - __uint_as_float(h1 << 16),
                                  v11 - __uint_as_float(h1 & 0xffff0000u));
        *(uint32_t*)(g_yh + (size_t)(gb + row_a) * DMODEL + col) = h0;
        *(uint32_t*)(g_yh + (size_t)(gb + row_b) * DMODEL + col) = h1;
        *(uint32_t*)(g_yl + (size_t)(gb + row_a) * DMODEL + col) = l0;
        *(uint32_t*)(g_yl + (size_t)(gb + row_b) * DMODEL + col) = l1;
    }
}

// ---------------------------------------------------------------------------
// Launch: x, mask, Wqkv, bqkv, Wo, bo -> out (B,L,D) f32
// ---------------------------------------------------------------------------
extern "C" void kernel_launch(void* const* d_in, const int* in_sizes, int n_in,
                              void* d_out, int out_size)
{
    const float* x    = (const float*)d_in[0];
    // d_in[1] = mask (exact causal; applied analytically)
    const float* Wqkv = (const float*)d_in[2];
    const float* bqkv = (const float*)d_in[3];
    const float* Wo   = (const float*)d_in[4];
    const float* bo   = (const float*)d_in[5];
    float* out        = (float*)d_out;

    __nv_bfloat16 *qkvh, *qkvl, *xh, *xl, *w1h, *w1l, *w2h, *w2l, *yh, *yl;
    cudaGetSymbolAddress((void**)&qkvh, g_qkvh);
    cudaGetSymbolAddress((void**)&qkvl, g_qkvl);
    cudaGetSymbolAddress((void**)&xh,  g_xh);
    cudaGetSymbolAddress((void**)&xl,  g_xl);
    cudaGetSymbolAddress((void**)&w1h, g_w1h);
    cudaGetSymbolAddress((void**)&w1l, g_w1l);
    cudaGetSymbolAddress((void**)&w2h, g_w2h);
    cudaGetSymbolAddress((void**)&w2l, g_w2l);
    cudaGetSymbolAddress((void**)&yh,  g_yh);
    cudaGetSymbolAddress((void**)&yl,  g_yl);

    cudaFuncSetAttribute(gemm_mma_split,
                         cudaFuncAttributeMaxDynamicSharedMemorySize, GEMM_SMEM);

    // 0) Split x; transpose+split weights
    {
        int n = MROWS * DMODEL;
        split_kernel<<<(n + 255) / 256, 256>>>(x, xh, xl, n);
        dim3 g1(D3 / 32, DMODEL / 32);
        transpose_split_kernel<<<g1, dim3(32, 8)>>>(Wqkv, w1h, w1l, DMODEL, D3);
        dim3 g2(DMODEL / 32, DMODEL / 32);
        transpose_split_kernel<<<g2, dim3(32, 8)>>>(Wo, w2h, w2l, DMODEL, DMODEL);
    }

    // 1) QKV projection -> split-bf16 qkv directly
    {
        dim3 grid(D3 / TB_N, MROWS / TB_M);   // (18, 32)
        gemm_mma_split<<<grid, 256, GEMM_SMEM>>>(xh, xl, w1h, w1l, bqkv,
                                                 nullptr, qkvh, qkvl,
                                                 MROWS, D3, DMODEL);
    }

    // 2) Causal attention on tensor cores -> split-bf16 y directly
    {
        dim3 grid(SEQ / 128, BATCH * NHEAD);  // (16, 24)
        attn3_kernel<<<grid, 256>>>();
    }

    // 3) Output projection -> f32 out
    {
        dim3 grid(DMODEL / TB_N, MROWS / TB_M);  // (6, 32)
        gemm_mma_split<<<grid, 256, GEMM_SMEM>>>(yh, yl, w2h, w2l, bo,
                                                 out, nullptr, nullptr,
                                                 MROWS, DMODEL, DMODEL);
    }
}

// round 10
// speedup vs baseline: 5.6892x; 1.1207x over previous
#include <cuda_runtime.h>
#include <cuda_bf16.h>
#include <cstdint>
#include <math.h>

// Problem constants
#define BATCH 2
#define SEQ   2048
#define DMODEL 768
#define NHEAD 12
#define DK    64
#define D3    (3*DMODEL)
#define MROWS (BATCH*SEQ)          // 4096
#define SCALE_LOG2E 0.1803368801111204f   // 0.125 * log2(e)

// ---------------------------------------------------------------------------
// Scratch (device globals; no allocation allowed)
// ---------------------------------------------------------------------------
__device__ __nv_bfloat16 g_qkvh[(size_t)MROWS * D3];   // split qkv (high)
__device__ __nv_bfloat16 g_qkvl[(size_t)MROWS * D3];   // split qkv (low)
__device__ __nv_bfloat16 g_xh[(size_t)MROWS * DMODEL];
__device__ __nv_bfloat16 g_xl[(size_t)MROWS * DMODEL];
__device__ __nv_bfloat16 g_w1h[(size_t)D3 * DMODEL];   // Wqkv^T [2304, 768]
__device__ __nv_bfloat16 g_w1l[(size_t)D3 * DMODEL];
__device__ __nv_bfloat16 g_w2h[(size_t)DMODEL * DMODEL]; // Wo^T
__device__ __nv_bfloat16 g_w2l[(size_t)DMODEL * DMODEL];
__device__ __nv_bfloat16 g_yh[(size_t)MROWS * DMODEL];
__device__ __nv_bfloat16 g_yl[(size_t)MROWS * DMODEL];

// ---------------------------------------------------------------------------
// Portable tensor-core helpers (sm_80-era PTX)
// ---------------------------------------------------------------------------
__device__ __forceinline__ uint32_t smem_u32(const void* p) {
    uint32_t a;
    asm("{ .reg .u64 t; cvta.to.shared.u64 t, %1; cvt.u32.u64 %0, t; }"
        : "=r"(a) : "l"(p));
    return a;
}
__device__ __forceinline__ void ldsm_x4(uint32_t& r0, uint32_t& r1,
                                        uint32_t& r2, uint32_t& r3, uint32_t addr) {
    asm volatile("ldmatrix.sync.aligned.m8n8.x4.shared.b16 {%0,%1,%2,%3}, [%4];"
                 : "=r"(r0), "=r"(r1), "=r"(r2), "=r"(r3) : "r"(addr));
}
__device__ __forceinline__ void ldsm_x4_t(uint32_t& r0, uint32_t& r1,
                                          uint32_t& r2, uint32_t& r3, uint32_t addr) {
    asm volatile("ldmatrix.sync.aligned.m8n8.x4.trans.shared.b16 {%0,%1,%2,%3}, [%4];"
                 : "=r"(r0), "=r"(r1), "=r"(r2), "=r"(r3) : "r"(addr));
}
__device__ __forceinline__ void mma16816(float* c, const uint32_t* a, const uint32_t* b) {
    asm volatile(
        "mma.sync.aligned.m16n8k16.row.col.f32.bf16.bf16.f32 "
        "{%0,%1,%2,%3}, {%4,%5,%6,%7}, {%8,%9}, {%0,%1,%2,%3};"
        : "+f"(c[0]), "+f"(c[1]), "+f"(c[2]), "+f"(c[3])
        : "r"(a[0]), "r"(a[1]), "r"(a[2]), "r"(a[3]), "r"(b[0]), "r"(b[1]));
}
// pack (lo, hi) floats into bf16x2 register
__device__ __forceinline__ uint32_t pack_bf16x2(float lo, float hi) {
    uint32_t r;
    asm("cvt.rn.bf16x2.f32 %0, %1, %2;" : "=r"(r) : "f"(hi), "f"(lo));
    return r;
}

// ---------------------------------------------------------------------------
// Conversion kernels
// ---------------------------------------------------------------------------
__global__ void split_kernel(const float* __restrict__ in,
                             __nv_bfloat16* __restrict__ h,
                             __nv_bfloat16* __restrict__ l, int n)
{
    int i = blockIdx.x * blockDim.x + threadIdx.x;
    if (i < n) {
        float x = in[i];
        __nv_bfloat16 hh = __float2bfloat16(x);
        h[i] = hh;
        l[i] = __float2bfloat16(x - __bfloat162float(hh));
    }
}

__global__ void transpose_split_kernel(const float* __restrict__ W,
                                       __nv_bfloat16* __restrict__ Th,
                                       __nv_bfloat16* __restrict__ Tl,
                                       int K, int N)
{
    __shared__ float t[32][33];
    const int n0 = blockIdx.x * 32, k0 = blockIdx.y * 32;
    const int tx = threadIdx.x, ty = threadIdx.y;   // (32, 8)
#pragma unroll
    for (int i = 0; i < 32; i += 8)
        t[ty + i][tx] = W[(size_t)(k0 + ty + i) * N + n0 + tx];
    __syncthreads();
#pragma unroll
    for (int i = 0; i < 32; i += 8) {
        float x = t[tx][ty + i];
        __nv_bfloat16 hh = __float2bfloat16(x);
        size_t o = (size_t)(n0 + ty + i) * K + k0 + tx;
        Th[o] = hh;
        Tl[o] = __float2bfloat16(x - __bfloat162float(hh));
    }
}

// ---------------------------------------------------------------------------
// Split-bf16 GEMM on mma.sync. Output either f32 C (+bias), or split-bf16
// (Ch, Cl) when Ch != nullptr.  minBlocksPerMultiprocessor=2 caps regs at 128
// (R6 post-mortem: 138 regs -> 1 CTA/SM -> 50% slower).
// ---------------------------------------------------------------------------
#define TB_M 128
#define TB_N 128
#define TB_K 64
#define SMS  72
#define TILE_ELEMS (128 * SMS)
#define GEMM_SMEM  (4 * TILE_ELEMS * 2)   // 73728 B

__global__ __launch_bounds__(256, 2)
void gemm_mma_split(const __nv_bfloat16* __restrict__ Ah,
                    const __nv_bfloat16* __restrict__ Al,
                    const __nv_bfloat16* __restrict__ Bth,
                    const __nv_bfloat16* __restrict__ Btl,
                    const float* __restrict__ bias,
                    float* __restrict__ C,
                    __nv_bfloat16* __restrict__ Ch,
                    __nv_bfloat16* __restrict__ Cl,
                    int M, int N, int K)
{
    extern __shared__ __nv_bfloat16 smg[];
    __nv_bfloat16* sAh = smg;
    __nv_bfloat16* sAl = smg + TILE_ELEMS;
    __nv_bfloat16* sBh = smg + 2 * TILE_ELEMS;
    __nv_bfloat16* sBl = smg + 3 * TILE_ELEMS;

    const int tid  = threadIdx.x;
    const int wid  = tid >> 5;
    const int lane = tid & 31;
    const int wm   = wid >> 2;
    const int wn   = wid & 3;
    const int m0   = blockIdx.y * TB_M;
    const int n0   = blockIdx.x * TB_N;

    float acc[4][4][4];
#pragma unroll
    for (int i = 0; i < 4; i++)
#pragma unroll
        for (int j = 0; j < 4; j++)
#pragma unroll
            for (int e = 0; e < 4; e++) acc[i][j][e] = 0.0f;

    const int a_row = lane & 15;
    const int a_col = (lane >> 4) * 8;
    const int b_row = (lane >> 4) * 8 + (lane & 7);
    const int b_col = ((lane >> 3) & 1) * 8;

    const uint32_t sAh_u = smem_u32(sAh);
    const uint32_t sAl_u = smem_u32(sAl);
    const uint32_t sBh_u = smem_u32(sBh);
    const uint32_t sBl_u = smem_u32(sBl);

    const int nchunks = K / TB_K;
    for (int c = 0; c < nchunks; c++) {
        const int k0 = c * TB_K;
        __syncthreads();
#pragma unroll
        for (int t = 0; t < 4; t++) {
            const __nv_bfloat16* src;
            __nv_bfloat16* dst;
            int rbase;
            if (t == 0)      { src = Ah;  dst = sAh; rbase = m0; }
            else if (t == 1) { src = Al;  dst = sAl; rbase = m0; }
            else if (t == 2) { src = Bth; dst = sBh; rbase = n0; }
            else             { src = Btl; dst = sBl; rbase = n0; }
#pragma unroll
            for (int s = tid; s < 1024; s += 256) {
                int row = s >> 3;
                int c8  = s & 7;
                uint4 v = *(const uint4*)(src + (size_t)(rbase + row) * K + k0 + c8 * 8);
                *(uint4*)(dst + row * SMS + c8 * 8) = v;
            }
        }
        __syncthreads();

#pragma unroll
        for (int ks = 0; ks < 4; ks++) {
            uint32_t ah[4][4], al[4][4], bh[4][2], bl[4][2];
#pragma unroll
            for (int i = 0; i < 4; i++) {
                uint32_t off = ((wm * 64 + i * 16 + a_row) * SMS + ks * 16 + a_col) * 2;
                ldsm_x4(ah[i][0], ah[i][1], ah[i][2], ah[i][3], sAh_u + off);
                ldsm_x4(al[i][0], al[i][1], al[i][2], al[i][3], sAl_u + off);
            }
#pragma unroll
            for (int jp = 0; jp < 2; jp++) {
                uint32_t off = ((wn * 32 + jp * 16 + b_row) * SMS + ks * 16 + b_col) * 2;
                ldsm_x4(bh[jp*2][0], bh[jp*2][1], bh[jp*2+1][0], bh[jp*2+1][1], sBh_u + off);
                ldsm_x4(bl[jp*2][0], bl[jp*2][1], bl[jp*2+1][0], bl[jp*2+1][1], sBl_u + off);
            }
#pragma unroll
            for (int i = 0; i < 4; i++)
#pragma unroll
                for (int j = 0; j < 4; j++) {
                    mma16816(acc[i][j], ah[i], bh[j]);
                    mma16816(acc[i][j], ah[i], bl[j]);
                    mma16816(acc[i][j], al[i], bh[j]);
                }
        }
    }

    const int cr = lane >> 2;
    const int cc = (lane & 3) * 2;
#pragma unroll
    for (int i = 0; i < 4; i++) {
#pragma unroll
        for (int j = 0; j < 4; j++) {
            int row = m0 + wm * 64 + i * 16 + cr;
            int col = n0 + wn * 32 + j * 8 + cc;
            float b0 = __ldg(bias + col), b1 = __ldg(bias + col + 1);
            float v00 = acc[i][j][0] + b0, v01 = acc[i][j][1] + b1;
            float v10 = acc[i][j][2] + b0, v11 = acc[i][j][3] + b1;
            if (Ch) {
                uint32_t h0 = pack_bf16x2(v00, v01);
                uint32_t h1 = pack_bf16x2(v10, v11);
                uint32_t l0 = pack_bf16x2(v00 - __uint_as_float(h0 << 16),
                                          v01 - __uint_as_float(h0 & 0xffff0000u));
                uint32_t l1 = pack_bf16x2(v10 - __uint_as_float(h1 << 16),
                                          v11 - __uint_as_float(h1 & 0xffff0000u));
                *(uint32_t*)(Ch + (size_t)row * N + col) = h0;
                *(uint32_t*)(Ch + (size_t)(row + 8) * N + col) = h1;
                *(uint32_t*)(Cl + (size_t)row * N + col) = l0;
                *(uint32_t*)(Cl + (size_t)(row + 8) * N + col) = l1;
            } else {
                *(float2*)(C + (size_t)row * N + col) = make_float2(v00, v01);
                *(float2*)(C + (size_t)(row + 8) * N + col) = make_float2(v10, v11);
            }
        }
    }
}

// ---------------------------------------------------------------------------
// Causal flash attention on mma.sync, split-bf16 everywhere.
// ---------------------------------------------------------------------------
#define VST 72
#define ATT_SMEM_ELEMS (4 * 64 * VST)    // 18432 bf16 = 36864 B

__global__ __launch_bounds__(256)
void attn3_kernel()
{
    __shared__ __nv_bfloat16 sm[ATT_SMEM_ELEMS];
    __nv_bfloat16* sKh = sm;
    __nv_bfloat16* sKl = sm + 64 * VST;
    __nv_bfloat16* sVh = sm + 2 * 64 * VST;
    __nv_bfloat16* sVl = sm + 3 * 64 * VST;

    const int tid  = threadIdx.x;
    const int wq   = tid >> 5;
    const int lane = tid & 31;
    const int bh   = blockIdx.y;
    const int b    = bh / NHEAD;
    const int h    = bh % NHEAD;
    const int q0   = (gridDim.x - 1 - blockIdx.x) * 128;   // heavy blocks first

    const int a_row = lane & 15;
    const int a_col = (lane >> 4) * 8;
    const int b_row = (lane >> 4) * 8 + (lane & 7);
    const int b_col = ((lane >> 3) & 1) * 8;
    const int cr = lane >> 2;
    const int cc = (lane & 3) * 2;

    // ---- Stage Q tile (128 x 64, h & l) into smem, then frags to registers
    {
        const __nv_bfloat16* qh_src = g_qkvh + (size_t)(b * SEQ + q0) * D3 + h * DK;
        const __nv_bfloat16* ql_src = g_qkvl + (size_t)(b * SEQ + q0) * D3 + h * DK;
        for (int s = tid; s < 1024; s += 256) {
            int row = s >> 3;
            int c8  = s & 7;
            *(uint4*)(sm + row * VST + c8 * 8) =
                *(const uint4*)(qh_src + (size_t)row * D3 + c8 * 8);
            *(uint4*)(sm + 128 * VST + row * VST + c8 * 8) =
                *(const uint4*)(ql_src + (size_t)row * D3 + c8 * 8);
        }
    }
    __syncthreads();

    uint32_t qfh[4][4], qfl[4][4];
    {
        const uint32_t sq = smem_u32(sm);
#pragma unroll
        for (int t = 0; t < 4; t++) {
            uint32_t off = ((wq * 16 + a_row) * VST + t * 16 + a_col) * 2;
            ldsm_x4(qfh[t][0], qfh[t][1], qfh[t][2], qfh[t][3], sq + off);
            ldsm_x4(qfl[t][0], qfl[t][1], qfl[t][2], qfl[t][3],
                    sq + 128 * VST * 2 + off);
        }
    }
    __syncthreads();

    float oacc[8][4];
#pragma unroll
    for (int j = 0; j < 8; j++)
#pragma unroll
        for (int e = 0; e < 4; e++) oacc[j][e] = 0.0f;
    float mrow[2] = {-1e30f, -1e30f};
    float lrow[2] = {0.0f, 0.0f};

    const uint32_t sKh_u = smem_u32(sKh), sKl_u = smem_u32(sKl);
    const uint32_t sVh_u = smem_u32(sVh), sVl_u = smem_u32(sVl);
    const int warp_row_min = q0 + wq * 16;
    const int nkt = q0 / 64 + 2;

    for (int kt = 0; kt < nkt; kt++) {
        const int k0 = kt * 64;

        // Load K/V tiles (split bf16) into smem
        {
            const size_t base = (size_t)(b * SEQ + k0) * D3 + h * DK;
            for (int s = tid; s < 512; s += 256) {
                int row = s >> 3;
                int c8  = s & 7;
                size_t g = base + (size_t)row * D3 + c8 * 8;
                int so = row * VST + c8 * 8;
                *(uint4*)(sKh + so) = *(const uint4*)(g_qkvh + g + DMODEL);
                *(uint4*)(sKl + so) = *(const uint4*)(g_qkvl + g + DMODEL);
                *(uint4*)(sVh + so) = *(const uint4*)(g_qkvh + g + 2 * DMODEL);
                *(uint4*)(sVl + so) = *(const uint4*)(g_qkvl + g + 2 * DMODEL);
            }
        }
        __syncthreads();

        if (k0 <= warp_row_min + 15) {   // warp has at least one unmasked key
            // ---- S = Q K^T (16 x 64 per warp), 3-product split
            float sacc[8][4];
#pragma unroll
            for (int j = 0; j < 8; j++)
#pragma unroll
                for (int e = 0; e < 4; e++) sacc[j][e] = 0.0f;

#pragma unroll
            for (int t = 0; t < 4; t++) {
                uint32_t kbh[8][2], kbl[8][2];
#pragma unroll
                for (int jp = 0; jp < 4; jp++) {
                    uint32_t off = ((jp * 16 + b_row) * VST + t * 16 + b_col) * 2;
                    ldsm_x4(kbh[jp*2][0], kbh[jp*2][1], kbh[jp*2+1][0], kbh[jp*2+1][1],
                            sKh_u + off);
                    ldsm_x4(kbl[jp*2][0], kbl[jp*2][1], kbl[jp*2+1][0], kbl[jp*2+1][1],
                            sKl_u + off);
                }
#pragma unroll
                for (int j = 0; j < 8; j++) {
                    mma16816(sacc[j], qfh[t], kbh[j]);
                    mma16816(sacc[j], qfh[t], kbl[j]);
                    mma16816(sacc[j], qfl[t], kbh[j]);
                }
            }

            // scale to base-2 domain; causal mask on diagonal-crossing tiles
#pragma unroll
            for (int j = 0; j < 8; j++)
#pragma unroll
                for (int e = 0; e < 4; e++) sacc[j][e] *= SCALE_LOG2E;

            if (k0 + 63 > warp_row_min) {
#pragma unroll
                for (int j = 0; j < 8; j++)
#pragma unroll
                    for (int e = 0; e < 4; e++) {
                        int key = k0 + j * 8 + cc + (e & 1);
                        int row = warp_row_min + cr + ((e >> 1) * 8);
                        if (key > row) sacc[j][e] = -1e30f;
                    }
            }

            // ---- online softmax (rows cr and cr+8; 4 lanes per row)
#pragma unroll
            for (int r = 0; r < 2; r++) {
                float mt = -1e30f;
#pragma unroll
                for (int j = 0; j < 8; j++)
                    mt = fmaxf(mt, fmaxf(sacc[j][2*r], sacc[j][2*r+1]));
                mt = fmaxf(mt, __shfl_xor_sync(0xffffffffu, mt, 1));
                mt = fmaxf(mt, __shfl_xor_sync(0xffffffffu, mt, 2));

                float mn = fmaxf(mrow[r], mt);
                float c  = exp2f(mrow[r] - mn);
                mrow[r] = mn;
                lrow[r] *= c;
#pragma unroll
                for (int j = 0; j < 8; j++) {
                    oacc[j][2*r]   *= c;
                    oacc[j][2*r+1] *= c;
                }
                float rs = 0.0f;
#pragma unroll
                for (int j = 0; j < 8; j++) {
                    float p0 = exp2f(sacc[j][2*r]   - mn);
                    float p1 = exp2f(sacc[j][2*r+1] - mn);
                    sacc[j][2*r]   = p0;
                    sacc[j][2*r+1] = p1;
                    rs += p0 + p1;
                }
                lrow[r] += rs;
            }

            // ---- O += P V  (P frags from registers, V via ldmatrix.trans)
#pragma unroll
            for (int t = 0; t < 4; t++) {
                uint32_t pah[4], pal[4];
#pragma unroll
                for (int half = 0; half < 2; half++) {
                    int j = 2 * t + half;
                    uint32_t h0 = pack_bf16x2(sacc[j][0], sacc[j][1]);
                    uint32_t h1 = pack_bf16x2(sacc[j][2], sacc[j][3]);
                    pah[half*2]   = h0;
                    pah[half*2+1] = h1;
                    pal[half*2]   = pack_bf16x2(
                        sacc[j][0] - __uint_as_float(h0 << 16),
                        sacc[j][1] - __uint_as_float(h0 & 0xffff0000u));
                    pal[half*2+1] = pack_bf16x2(
                        sacc[j][2] - __uint_as_float(h1 << 16),
                        sacc[j][3] - __uint_as_float(h1 & 0xffff0000u));
                }
                uint32_t vbh[8][2], vbl[8][2];
#pragma unroll
                for (int dp = 0; dp < 4; dp++) {
                    uint32_t off = ((t * 16 + (lane & 15)) * VST + dp * 16 + (lane >> 4) * 8) * 2;
                    ldsm_x4_t(vbh[dp*2][0], vbh[dp*2][1], vbh[dp*2+1][0], vbh[dp*2+1][1],
                              sVh_u + off);
                    ldsm_x4_t(vbl[dp*2][0], vbl[dp*2][1], vbl[dp*2+1][0], vbl[dp*2+1][1],
                              sVl_u + off);
                }
#pragma unroll
                for (int j = 0; j < 8; j++) {
                    mma16816(oacc[j], pah, vbh[j]);
                    mma16816(oacc[j], pah, vbl[j]);
                    mma16816(oacc[j], pal, vbh[j]);
                }
            }
        }
        __syncthreads();
    }

    // ---- finalize
#pragma unroll
    for (int r = 0; r < 2; r++) {
        lrow[r] += __shfl_xor_sync(0xffffffffu, lrow[r], 1);
        lrow[r] += __shfl_xor_sync(0xffffffffu, lrow[r], 2);
    }
    const float inv0 = 1.0f / lrow[0];
    const float inv1 = 1.0f / lrow[1];
    const int row_a = q0 + wq * 16 + cr;
    const int row_b = row_a + 8;
    const int gb = b * SEQ;
#pragma unroll
    for (int j = 0; j < 8; j++) {
        int col = h * DK + j * 8 + cc;
        float v00 = oacc[j][0] * inv0, v01 = oacc[j][1] * inv0;
        float v10 = oacc[j][2] * inv1, v11 = oacc[j][3] * inv1;
        uint32_t h0 = pack_bf16x2(v00, v01);
        uint32_t h1 = pack_bf16x2(v10, v11);
        uint32_t l0 = pack_bf16x2(v00 - __uint_as_float(h0 << 16),
                                  v01 - __uint_as_float(h0 & 0xffff0000u));
        uint32_t l1 = pack_bf16x2(v10 - __uint_as_float(h1 << 16),
                                  v11 - __uint_as_float(h1 & 0xffff0000u));
        *(uint32_t*)(g_yh + (size_t)(gb + row_a) * DMODEL + col) = h0;
        *(uint32_t*)(g_yh + (size_t)(gb + row_b) * DMODEL + col) = h1;
        *(uint32_t*)(g_yl + (size_t)(gb + row_a) * DMODEL + col) = l0;
        *(uint32_t*)(g_yl + (size_t)(gb + row_b) * DMODEL + col) = l1;
    }
}

// ---------------------------------------------------------------------------
// Launch: x, mask, Wqkv, bqkv, Wo, bo -> out (B,L,D) f32
// ---------------------------------------------------------------------------
extern "C" void kernel_launch(void* const* d_in, const int* in_sizes, int n_in,
                              void* d_out, int out_size)
{
    const float* x    = (const float*)d_in[0];
    // d_in[1] = mask (exact causal; applied analytically)
    const float* Wqkv = (const float*)d_in[2];
    const float* bqkv = (const float*)d_in[3];
    const float* Wo   = (const float*)d_in[4];
    const float* bo   = (const float*)d_in[5];
    float* out        = (float*)d_out;

    __nv_bfloat16 *qkvh, *qkvl, *xh, *xl, *w1h, *w1l, *w2h, *w2l, *yh, *yl;
    cudaGetSymbolAddress((void**)&qkvh, g_qkvh);
    cudaGetSymbolAddress((void**)&qkvl, g_qkvl);
    cudaGetSymbolAddress((void**)&xh,  g_xh);
    cudaGetSymbolAddress((void**)&xl,  g_xl);
    cudaGetSymbolAddress((void**)&w1h, g_w1h);
    cudaGetSymbolAddress((void**)&w1l, g_w1l);
    cudaGetSymbolAddress((void**)&w2h, g_w2h);
    cudaGetSymbolAddress((void**)&w2l, g_w2l);
    cudaGetSymbolAddress((void**)&yh,  g_yh);
    cudaGetSymbolAddress((void**)&yl,  g_yl);

    cudaFuncSetAttribute(gemm_mma_split,
                         cudaFuncAttributeMaxDynamicSharedMemorySize, GEMM_SMEM);

    // 0) Split x; transpose+split weights
    {
        int n = MROWS * DMODEL;
        split_kernel<<<(n + 255) / 256, 256>>>(x, xh, xl, n);
        dim3 g1(D3 / 32, DMODEL / 32);
        transpose_split_kernel<<<g1, dim3(32, 8)>>>(Wqkv, w1h, w1l, DMODEL, D3);
        dim3 g2(DMODEL / 32, DMODEL / 32);
        transpose_split_kernel<<<g2, dim3(32, 8)>>>(Wo, w2h, w2l, DMODEL, DMODEL);
    }

    // 1) QKV projection -> split-bf16 qkv directly
    {
        dim3 grid(D3 / TB_N, MROWS / TB_M);   // (18, 32)
        gemm_mma_split<<<grid, 256, GEMM_SMEM>>>(xh, xl, w1h, w1l, bqkv,
                                                 nullptr, qkvh, qkvl,
                                                 MROWS, D3, DMODEL);
    }

    // 2) Causal attention on tensor cores -> split-bf16 y directly
    {
        dim3 grid(SEQ / 128, BATCH * NHEAD);  // (16, 24)
        attn3_kernel<<<grid, 256>>>();
    }

    // 3) Output projection -> f32 out
    {
        dim3 grid(DMODEL / TB_N, MROWS / TB_M);  // (6, 32)
        gemm_mma_split<<<grid, 256, GEMM_SMEM>>>(yh, yl, w2h, w2l, bo,
                                                 out, nullptr, nullptr,
                                                 MROWS, DMODEL, DMODEL);
    }
}

// round 12
// speedup vs baseline: 6.2432x; 1.0974x over previous
#include <cuda_runtime.h>
#include <cuda_bf16.h>
#include <cstdint>
#include <math.h>

// Problem constants
#define BATCH 2
#define SEQ   2048
#define DMODEL 768
#define NHEAD 12
#define DK    64
#define D3    (3*DMODEL)
#define MROWS (BATCH*SEQ)          // 4096
#define SCALE_LOG2E 0.1803368801111204f   // 0.125 * log2(e)

// ---------------------------------------------------------------------------
// Scratch (device globals; no allocation allowed)
// ---------------------------------------------------------------------------
__device__ __nv_bfloat16 g_qkvh[(size_t)MROWS * D3];   // split qkv (high)
__device__ __nv_bfloat16 g_qkvl[(size_t)MROWS * D3];   // split qkv (low)
__device__ __nv_bfloat16 g_xh[(size_t)MROWS * DMODEL];
__device__ __nv_bfloat16 g_xl[(size_t)MROWS * DMODEL];
__device__ __nv_bfloat16 g_w1h[(size_t)D3 * DMODEL];   // Wqkv^T [2304, 768]
__device__ __nv_bfloat16 g_w1l[(size_t)D3 * DMODEL];
__device__ __nv_bfloat16 g_w2h[(size_t)DMODEL * DMODEL]; // Wo^T
__device__ __nv_bfloat16 g_w2l[(size_t)DMODEL * DMODEL];
__device__ __nv_bfloat16 g_yh[(size_t)MROWS * DMODEL];
__device__ __nv_bfloat16 g_yl[(size_t)MROWS * DMODEL];

// ---------------------------------------------------------------------------
// Portable tensor-core / async helpers (sm_80-era PTX)
// ---------------------------------------------------------------------------
__device__ __forceinline__ uint32_t smem_u32(const void* p) {
    uint32_t a;
    asm("{ .reg .u64 t; cvta.to.shared.u64 t, %1; cvt.u32.u64 %0, t; }"
        : "=r"(a) : "l"(p));
    return a;
}
__device__ __forceinline__ void ldsm_x4(uint32_t& r0, uint32_t& r1,
                                        uint32_t& r2, uint32_t& r3, uint32_t addr) {
    asm volatile("ldmatrix.sync.aligned.m8n8.x4.shared.b16 {%0,%1,%2,%3}, [%4];"
                 : "=r"(r0), "=r"(r1), "=r"(r2), "=r"(r3) : "r"(addr));
}
__device__ __forceinline__ void ldsm_x4_t(uint32_t& r0, uint32_t& r1,
                                          uint32_t& r2, uint32_t& r3, uint32_t addr) {
    asm volatile("ldmatrix.sync.aligned.m8n8.x4.trans.shared.b16 {%0,%1,%2,%3}, [%4];"
                 : "=r"(r0), "=r"(r1), "=r"(r2), "=r"(r3) : "r"(addr));
}
__device__ __forceinline__ void mma16816(float* c, const uint32_t* a, const uint32_t* b) {
    asm volatile(
        "mma.sync.aligned.m16n8k16.row.col.f32.bf16.bf16.f32 "
        "{%0,%1,%2,%3}, {%4,%5,%6,%7}, {%8,%9}, {%0,%1,%2,%3};"
        : "+f"(c[0]), "+f"(c[1]), "+f"(c[2]), "+f"(c[3])
        : "r"(a[0]), "r"(a[1]), "r"(a[2]), "r"(a[3]), "r"(b[0]), "r"(b[1]));
}
__device__ __forceinline__ uint32_t pack_bf16x2(float lo, float hi) {
    uint32_t r;
    asm("cvt.rn.bf16x2.f32 %0, %1, %2;" : "=r"(r) : "f"(hi), "f"(lo));
    return r;
}
__device__ __forceinline__ void cp_async16(uint32_t smem_addr, const void* gptr) {
    asm volatile("cp.async.cg.shared.global [%0], [%1], 16;"
                 :: "r"(smem_addr), "l"(gptr) : "memory");
}
#define CP_COMMIT()  asm volatile("cp.async.commit_group;" ::: "memory")
#define CP_WAIT(n)   asm volatile("cp.async.wait_group %0;" :: "n"(n) : "memory")

// ---------------------------------------------------------------------------
// Conversion kernels
// ---------------------------------------------------------------------------
__global__ void split_kernel(const float* __restrict__ in,
                             __nv_bfloat16* __restrict__ h,
                             __nv_bfloat16* __restrict__ l, int n)
{
    int i = blockIdx.x * blockDim.x + threadIdx.x;
    if (i < n) {
        float x = in[i];
        __nv_bfloat16 hh = __float2bfloat16(x);
        h[i] = hh;
        l[i] = __float2bfloat16(x - __bfloat162float(hh));
    }
}

__global__ void transpose_split_kernel(const float* __restrict__ W,
                                       __nv_bfloat16* __restrict__ Th,
                                       __nv_bfloat16* __restrict__ Tl,
                                       int K, int N)
{
    __shared__ float t[32][33];
    const int n0 = blockIdx.x * 32, k0 = blockIdx.y * 32;
    const int tx = threadIdx.x, ty = threadIdx.y;   // (32, 8)
#pragma unroll
    for (int i = 0; i < 32; i += 8)
        t[ty + i][tx] = W[(size_t)(k0 + ty + i) * N + n0 + tx];
    __syncthreads();
#pragma unroll
    for (int i = 0; i < 32; i += 8) {
        float x = t[tx][ty + i];
        __nv_bfloat16 hh = __float2bfloat16(x);
        size_t o = (size_t)(n0 + ty + i) * K + k0 + tx;
        Th[o] = hh;
        Tl[o] = __float2bfloat16(x - __bfloat162float(hh));
    }
}

// ---------------------------------------------------------------------------
// Split-bf16 GEMM on mma.sync (unchanged from R10: 2 CTAs/SM, tensor 61%)
// ---------------------------------------------------------------------------
#define TB_M 128
#define TB_N 128
#define TB_K 64
#define SMS  72
#define TILE_ELEMS (128 * SMS)
#define GEMM_SMEM  (4 * TILE_ELEMS * 2)   // 73728 B

__global__ __launch_bounds__(256, 2)
void gemm_mma_split(const __nv_bfloat16* __restrict__ Ah,
                    const __nv_bfloat16* __restrict__ Al,
                    const __nv_bfloat16* __restrict__ Bth,
                    const __nv_bfloat16* __restrict__ Btl,
                    const float* __restrict__ bias,
                    float* __restrict__ C,
                    __nv_bfloat16* __restrict__ Ch,
                    __nv_bfloat16* __restrict__ Cl,
                    int M, int N, int K)
{
    extern __shared__ __nv_bfloat16 smg[];
    __nv_bfloat16* sAh = smg;
    __nv_bfloat16* sAl = smg + TILE_ELEMS;
    __nv_bfloat16* sBh = smg + 2 * TILE_ELEMS;
    __nv_bfloat16* sBl = smg + 3 * TILE_ELEMS;

    const int tid  = threadIdx.x;
    const int wid  = tid >> 5;
    const int lane = tid & 31;
    const int wm   = wid >> 2;
    const int wn   = wid & 3;
    const int m0   = blockIdx.y * TB_M;
    const int n0   = blockIdx.x * TB_N;

    float acc[4][4][4];
#pragma unroll
    for (int i = 0; i < 4; i++)
#pragma unroll
        for (int j = 0; j < 4; j++)
#pragma unroll
            for (int e = 0; e < 4; e++) acc[i][j][e] = 0.0f;

    const int a_row = lane & 15;
    const int a_col = (lane >> 4) * 8;
    const int b_row = (lane >> 4) * 8 + (lane & 7);
    const int b_col = ((lane >> 3) & 1) * 8;

    const uint32_t sAh_u = smem_u32(sAh);
    const uint32_t sAl_u = smem_u32(sAl);
    const uint32_t sBh_u = smem_u32(sBh);
    const uint32_t sBl_u = smem_u32(sBl);

    const int nchunks = K / TB_K;
    for (int c = 0; c < nchunks; c++) {
        const int k0 = c * TB_K;
        __syncthreads();
#pragma unroll
        for (int t = 0; t < 4; t++) {
            const __nv_bfloat16* src;
            __nv_bfloat16* dst;
            int rbase;
            if (t == 0)      { src = Ah;  dst = sAh; rbase = m0; }
            else if (t == 1) { src = Al;  dst = sAl; rbase = m0; }
            else if (t == 2) { src = Bth; dst = sBh; rbase = n0; }
            else             { src = Btl; dst = sBl; rbase = n0; }
#pragma unroll
            for (int s = tid; s < 1024; s += 256) {
                int row = s >> 3;
                int c8  = s & 7;
                uint4 v = *(const uint4*)(src + (size_t)(rbase + row) * K + k0 + c8 * 8);
                *(uint4*)(dst + row * SMS + c8 * 8) = v;
            }
        }
        __syncthreads();

#pragma unroll
        for (int ks = 0; ks < 4; ks++) {
            uint32_t ah[4][4], al[4][4], bh[4][2], bl[4][2];
#pragma unroll
            for (int i = 0; i < 4; i++) {
                uint32_t off = ((wm * 64 + i * 16 + a_row) * SMS + ks * 16 + a_col) * 2;
                ldsm_x4(ah[i][0], ah[i][1], ah[i][2], ah[i][3], sAh_u + off);
                ldsm_x4(al[i][0], al[i][1], al[i][2], al[i][3], sAl_u + off);
            }
#pragma unroll
            for (int jp = 0; jp < 2; jp++) {
                uint32_t off = ((wn * 32 + jp * 16 + b_row) * SMS + ks * 16 + b_col) * 2;
                ldsm_x4(bh[jp*2][0], bh[jp*2][1], bh[jp*2+1][0], bh[jp*2+1][1], sBh_u + off);
                ldsm_x4(bl[jp*2][0], bl[jp*2][1], bl[jp*2+1][0], bl[jp*2+1][1], sBl_u + off);
            }
#pragma unroll
            for (int i = 0; i < 4; i++)
#pragma unroll
                for (int j = 0; j < 4; j++) {
                    mma16816(acc[i][j], ah[i], bh[j]);
                    mma16816(acc[i][j], ah[i], bl[j]);
                    mma16816(acc[i][j], al[i], bh[j]);
                }
        }
    }

    const int cr = lane >> 2;
    const int cc = (lane & 3) * 2;
#pragma unroll
    for (int i = 0; i < 4; i++) {
#pragma unroll
        for (int j = 0; j < 4; j++) {
            int row = m0 + wm * 64 + i * 16 + cr;
            int col = n0 + wn * 32 + j * 8 + cc;
            float b0 = __ldg(bias + col), b1 = __ldg(bias + col + 1);
            float v00 = acc[i][j][0] + b0, v01 = acc[i][j][1] + b1;
            float v10 = acc[i][j][2] + b0, v11 = acc[i][j][3] + b1;
            if (Ch) {
                uint32_t h0 = pack_bf16x2(v00, v01);
                uint32_t h1 = pack_bf16x2(v10, v11);
                uint32_t l0 = pack_bf16x2(v00 - __uint_as_float(h0 << 16),
                                          v01 - __uint_as_float(h0 & 0xffff0000u));
                uint32_t l1 = pack_bf16x2(v10 - __uint_as_float(h1 << 16),
                                          v11 - __uint_as_float(h1 & 0xffff0000u));
                *(uint32_t*)(Ch + (size_t)row * N + col) = h0;
                *(uint32_t*)(Ch + (size_t)(row + 8) * N + col) = h1;
                *(uint32_t*)(Cl + (size_t)row * N + col) = l0;
                *(uint32_t*)(Cl + (size_t)(row + 8) * N + col) = l1;
            } else {
                *(float2*)(C + (size_t)row * N + col) = make_float2(v00, v01);
                *(float2*)(C + (size_t)(row + 8) * N + col) = make_float2(v10, v11);
            }
        }
    }
}

// ---------------------------------------------------------------------------
// Causal flash attention on mma.sync, split-bf16, cp.async double-buffered
// K/V pipeline (R11). Two 36.9KB stages; prefetch tile kt+1 during compute.
// ---------------------------------------------------------------------------
#define VST 72
#define TILE_B  (64 * VST * 2)        // 9216 B per K/V sub-tile
#define STAGE_B (4 * TILE_B)          // 36864 B per stage
#define ATTN_SMEM (2 * STAGE_B)       // 73728 B

__global__ __launch_bounds__(256)
void attn3_kernel()
{
    extern __shared__ __nv_bfloat16 smd[];
    const uint32_t sbase = smem_u32(smd);

    const int tid  = threadIdx.x;
    const int wq   = tid >> 5;
    const int lane = tid & 31;
    const int bh   = blockIdx.y;
    const int b    = bh / NHEAD;
    const int h    = bh % NHEAD;
    const int q0   = (gridDim.x - 1 - blockIdx.x) * 128;   // heavy blocks first

    const int a_row = lane & 15;
    const int a_col = (lane >> 4) * 8;
    const int b_row = (lane >> 4) * 8 + (lane & 7);
    const int b_col = ((lane >> 3) & 1) * 8;
    const int cr = lane >> 2;
    const int cc = (lane & 3) * 2;

    // ---- Stage Q (128x64 h+l) into stage-0 smem, pull frags to registers
    {
        const __nv_bfloat16* qh_src = g_qkvh + (size_t)(b * SEQ + q0) * D3 + h * DK;
        const __nv_bfloat16* ql_src = g_qkvl + (size_t)(b * SEQ + q0) * D3 + h * DK;
        for (int s = tid; s < 1024; s += 256) {
            int row = s >> 3;
            int c8  = s & 7;
            *(uint4*)(smd + row * VST + c8 * 8) =
                *(const uint4*)(qh_src + (size_t)row * D3 + c8 * 8);
            *(uint4*)(smd + 128 * VST + row * VST + c8 * 8) =
                *(const uint4*)(ql_src + (size_t)row * D3 + c8 * 8);
        }
    }
    __syncthreads();

    uint32_t qfh[4][4], qfl[4][4];
#pragma unroll
    for (int t = 0; t < 4; t++) {
        uint32_t off = ((wq * 16 + a_row) * VST + t * 16 + a_col) * 2;
        ldsm_x4(qfh[t][0], qfh[t][1], qfh[t][2], qfh[t][3], sbase + off);
        ldsm_x4(qfl[t][0], qfl[t][1], qfl[t][2], qfl[t][3],
                sbase + 128 * VST * 2 + off);
    }
    __syncthreads();   // Q frags read; stage 0 may be overwritten by prefetch

    float oacc[8][4];
#pragma unroll
    for (int j = 0; j < 8; j++)
#pragma unroll
        for (int e = 0; e < 4; e++) oacc[j][e] = 0.0f;
    float mrow[2] = {-1e30f, -1e30f};
    float lrow[2] = {0.0f, 0.0f};

    const int warp_row_min = q0 + wq * 16;
    const int nkt = q0 / 64 + 2;
    const size_t bh_base = (size_t)(b * SEQ) * D3 + h * DK;

    // async loader: K/V tile at key offset k0 into stage st
    auto load_tile = [&](int k0, int st) {
        const size_t base = bh_base + (size_t)k0 * D3;
        const uint32_t stage = sbase + st * STAGE_B;
#pragma unroll
        for (int s = tid; s < 512; s += 256) {
            int row = s >> 3;
            int c8  = s & 7;
            size_t g = base + (size_t)row * D3 + c8 * 8;
            uint32_t so = stage + (uint32_t)(row * VST + c8 * 8) * 2;
            cp_async16(so,              g_qkvh + g + DMODEL);        // Kh
            cp_async16(so + TILE_B,     g_qkvl + g + DMODEL);        // Kl
            cp_async16(so + 2 * TILE_B, g_qkvh + g + 2 * DMODEL);    // Vh
            cp_async16(so + 3 * TILE_B, g_qkvl + g + 2 * DMODEL);    // Vl
        }
    };

    // prologue
    load_tile(0, 0);
    CP_COMMIT();

    for (int kt = 0; kt < nkt; kt++) {
        const int k0 = kt * 64;
        if (kt + 1 < nkt) {
            load_tile((kt + 1) * 64, (kt + 1) & 1);
            CP_COMMIT();
            CP_WAIT(1);          // tile kt landed; kt+1 in flight
        } else {
            CP_WAIT(0);
        }
        __syncthreads();

        const uint32_t stage = sbase + (kt & 1) * STAGE_B;
        const uint32_t sKh_u = stage;
        const uint32_t sKl_u = stage + TILE_B;
        const uint32_t sVh_u = stage + 2 * TILE_B;
        const uint32_t sVl_u = stage + 3 * TILE_B;

        if (k0 <= warp_row_min + 15) {   // warp has at least one unmasked key
            // ---- S = Q K^T (16 x 64 per warp), 3-product split
            float sacc[8][4];
#pragma unroll
            for (int j = 0; j < 8; j++)
#pragma unroll
                for (int e = 0; e < 4; e++) sacc[j][e] = 0.0f;

#pragma unroll
            for (int t = 0; t < 4; t++) {
                uint32_t kbh[8][2], kbl[8][2];
#pragma unroll
                for (int jp = 0; jp < 4; jp++) {
                    uint32_t off = ((jp * 16 + b_row) * VST + t * 16 + b_col) * 2;
                    ldsm_x4(kbh[jp*2][0], kbh[jp*2][1], kbh[jp*2+1][0], kbh[jp*2+1][1],
                            sKh_u + off);
                    ldsm_x4(kbl[jp*2][0], kbl[jp*2][1], kbl[jp*2+1][0], kbl[jp*2+1][1],
                            sKl_u + off);
                }
#pragma unroll
                for (int j = 0; j < 8; j++) {
                    mma16816(sacc[j], qfh[t], kbh[j]);
                    mma16816(sacc[j], qfh[t], kbl[j]);
                    mma16816(sacc[j], qfl[t], kbh[j]);
                }
            }

            // scale to base-2 domain; causal mask on diagonal-crossing tiles
#pragma unroll
            for (int j = 0; j < 8; j++)
#pragma unroll
                for (int e = 0; e < 4; e++) sacc[j][e] *= SCALE_LOG2E;

            if (k0 + 63 > warp_row_min) {
#pragma unroll
                for (int j = 0; j < 8; j++)
#pragma unroll
                    for (int e = 0; e < 4; e++) {
                        int key = k0 + j * 8 + cc + (e & 1);
                        int row = warp_row_min + cr + ((e >> 1) * 8);
                        if (key > row) sacc[j][e] = -1e30f;
                    }
            }

            // ---- online softmax (rows cr and cr+8; 4 lanes per row)
#pragma unroll
            for (int r = 0; r < 2; r++) {
                float mt = -1e30f;
#pragma unroll
                for (int j = 0; j < 8; j++)
                    mt = fmaxf(mt, fmaxf(sacc[j][2*r], sacc[j][2*r+1]));
                mt = fmaxf(mt, __shfl_xor_sync(0xffffffffu, mt, 1));
                mt = fmaxf(mt, __shfl_xor_sync(0xffffffffu, mt, 2));

                float mn = fmaxf(mrow[r], mt);
                float c  = exp2f(mrow[r] - mn);
                mrow[r] = mn;
                lrow[r] *= c;
#pragma unroll
                for (int j = 0; j < 8; j++) {
                    oacc[j][2*r]   *= c;
                    oacc[j][2*r+1] *= c;
                }
                float rs = 0.0f;
#pragma unroll
                for (int j = 0; j < 8; j++) {
                    float p0 = exp2f(sacc[j][2*r]   - mn);
                    float p1 = exp2f(sacc[j][2*r+1] - mn);
                    sacc[j][2*r]   = p0;
                    sacc[j][2*r+1] = p1;
                    rs += p0 + p1;
                }
                lrow[r] += rs;
            }

            // ---- O += P V  (P frags from registers, V via ldmatrix.trans)
#pragma unroll
            for (int t = 0; t < 4; t++) {
                uint32_t pah[4], pal[4];
#pragma unroll
                for (int half = 0; half < 2; half++) {
                    int j = 2 * t + half;
                    uint32_t h0 = pack_bf16x2(sacc[j][0], sacc[j][1]);
                    uint32_t h1 = pack_bf16x2(sacc[j][2], sacc[j][3]);
                    pah[half*2]   = h0;
                    pah[half*2+1] = h1;
                    pal[half*2]   = pack_bf16x2(
                        sacc[j][0] - __uint_as_float(h0 << 16),
                        sacc[j][1] - __uint_as_float(h0 & 0xffff0000u));
                    pal[half*2+1] = pack_bf16x2(
                        sacc[j][2] - __uint_as_float(h1 << 16),
                        sacc[j][3] - __uint_as_float(h1 & 0xffff0000u));
                }
                uint32_t vbh[8][2], vbl[8][2];
#pragma unroll
                for (int dp = 0; dp < 4; dp++) {
                    uint32_t off = ((t * 16 + (lane & 15)) * VST + dp * 16 + (lane >> 4) * 8) * 2;
                    ldsm_x4_t(vbh[dp*2][0], vbh[dp*2][1], vbh[dp*2+1][0], vbh[dp*2+1][1],
                              sVh_u + off);
                    ldsm_x4_t(vbl[dp*2][0], vbl[dp*2][1], vbl[dp*2+1][0], vbl[dp*2+1][1],
                              sVl_u + off);
                }
#pragma unroll
                for (int j = 0; j < 8; j++) {
                    mma16816(oacc[j], pah, vbh[j]);
                    mma16816(oacc[j], pah, vbl[j]);
                    mma16816(oacc[j], pal, vbh[j]);
                }
            }
        }
        __syncthreads();   // all reads of this stage done before it is refilled
    }

    // ---- finalize
#pragma unroll
    for (int r = 0; r < 2; r++) {
        lrow[r] += __shfl_xor_sync(0xffffffffu, lrow[r], 1);
        lrow[r] += __shfl_xor_sync(0xffffffffu, lrow[r], 2);
    }
    const float inv0 = 1.0f / lrow[0];
    const float inv1 = 1.0f / lrow[1];
    const int row_a = q0 + wq * 16 + cr;
    const int row_b = row_a + 8;
    const int gb = b * SEQ;
#pragma unroll
    for (int j = 0; j < 8; j++) {
        int col = h * DK + j * 8 + cc;
        float v00 = oacc[j][0] * inv0, v01 = oacc[j][1] * inv0;
        float v10 = oacc[j][2] * inv1, v11 = oacc[j][3] * inv1;
        uint32_t h0 = pack_bf16x2(v00, v01);
        uint32_t h1 = pack_bf16x2(v10, v11);
        uint32_t l0 = pack_bf16x2(v00 - __uint_as_float(h0 << 16),
                                  v01 - __uint_as_float(h0 & 0xffff0000u));
        uint32_t l1 = pack_bf16x2(v10 - __uint_as_float(h1 << 16),
                                  v11 - __uint_as_float(h1 & 0xffff0000u));
        *(uint32_t*)(g_yh + (size_t)(gb + row_a) * DMODEL + col) = h0;
        *(uint32_t*)(g_yh + (size_t)(gb + row_b) * DMODEL + col) = h1;
        *(uint32_t*)(g_yl + (size_t)(gb + row_a) * DMODEL + col) = l0;
        *(uint32_t*)(g_yl + (size_t)(gb + row_b) * DMODEL + col) = l1;
    }
}

// ---------------------------------------------------------------------------
// Launch: x, mask, Wqkv, bqkv, Wo, bo -> out (B,L,D) f32
// ---------------------------------------------------------------------------
extern "C" void kernel_launch(void* const* d_in, const int* in_sizes, int n_in,
                              void* d_out, int out_size)
{
    const float* x    = (const float*)d_in[0];
    // d_in[1] = mask (exact causal; applied analytically)
    const float* Wqkv = (const float*)d_in[2];
    const float* bqkv = (const float*)d_in[3];
    const float* Wo   = (const float*)d_in[4];
    const float* bo   = (const float*)d_in[5];
    float* out        = (float*)d_out;

    __nv_bfloat16 *qkvh, *qkvl, *xh, *xl, *w1h, *w1l, *w2h, *w2l, *yh, *yl;
    cudaGetSymbolAddress((void**)&qkvh, g_qkvh);
    cudaGetSymbolAddress((void**)&qkvl, g_qkvl);
    cudaGetSymbolAddress((void**)&xh,  g_xh);
    cudaGetSymbolAddress((void**)&xl,  g_xl);
    cudaGetSymbolAddress((void**)&w1h, g_w1h);
    cudaGetSymbolAddress((void**)&w1l, g_w1l);
    cudaGetSymbolAddress((void**)&w2h, g_w2h);
    cudaGetSymbolAddress((void**)&w2l, g_w2l);
    cudaGetSymbolAddress((void**)&yh,  g_yh);
    cudaGetSymbolAddress((void**)&yl,  g_yl);

    cudaFuncSetAttribute(gemm_mma_split,
                         cudaFuncAttributeMaxDynamicSharedMemorySize, GEMM_SMEM);
    cudaFuncSetAttribute(attn3_kernel,
                         cudaFuncAttributeMaxDynamicSharedMemorySize, ATTN_SMEM);

    // 0) Split x; transpose+split weights
    {
        int n = MROWS * DMODEL;
        split_kernel<<<(n + 255) / 256, 256>>>(x, xh, xl, n);
        dim3 g1(D3 / 32, DMODEL / 32);
        transpose_split_kernel<<<g1, dim3(32, 8)>>>(Wqkv, w1h, w1l, DMODEL, D3);
        dim3 g2(DMODEL / 32, DMODEL / 32);
        transpose_split_kernel<<<g2, dim3(32, 8)>>>(Wo, w2h, w2l, DMODEL, DMODEL);
    }

    // 1) QKV projection -> split-bf16 qkv directly
    {
        dim3 grid(D3 / TB_N, MROWS / TB_M);   // (18, 32)
        gemm_mma_split<<<grid, 256, GEMM_SMEM>>>(xh, xl, w1h, w1l, bqkv,
                                                 nullptr, qkvh, qkvl,
                                                 MROWS, D3, DMODEL);
    }

    // 2) Causal attention, cp.async double-buffered -> split-bf16 y
    {
        dim3 grid(SEQ / 128, BATCH * NHEAD);  // (16, 24)
        attn3_kernel<<<grid, 256, ATTN_SMEM>>>();
    }

    // 3) Output projection -> f32 out
    {
        dim3 grid(DMODEL / TB_N, MROWS / TB_M);  // (6, 32)
        gemm_mma_split<<<grid, 256, GEMM_SMEM>>>(yh, yl, w2h, w2l, bo,
                                                 out, nullptr, nullptr,
                                                 MROWS, DMODEL, DMODEL);
    }
}